// round 6
// baseline (speedup 1.0000x reference)
#include <cuda_runtime.h>
#include <math.h>

#define T_STEPS 512
#define BATCH   64
#define IN_F    512
#define HID     512
#define GATES   1024
#define SCAN_CTAS 128
#define SCAN_THREADS 512

#define WPADF   516                    // 512 + 4 floats pad (W rows, 16B-aligned stride)
#define HSTRIDE 129                    // h row stride in float4 (=516 floats)
#define SMEM_W_FLOATS (8 * WPADF)
#define SMEM_H_FLOAT4 (BATCH * HSTRIDE)
#define SMEM_RED_FLOATS (BATCH * 4 * 2)
#define SMEM_BYTES (SMEM_W_FLOATS * 4 + SMEM_H_FLOAT4 * 16 + SMEM_RED_FLOATS * 4)

// 128 MiB scratch for precomputed input gates gi[t][b][g]
__device__ float g_gi[(size_t)T_STEPS * BATCH * GATES];
__device__ unsigned int g_bar;                     // arrival counter (zero at load)
__device__ unsigned int g_flags[SCAN_CTAS * 32];   // per-CTA epoch flags, 128B apart

__device__ __forceinline__ unsigned ld_acquire_gpu(const unsigned* p) {
    unsigned v;
    asm volatile("ld.acquire.gpu.global.u32 %0, [%1];" : "=r"(v) : "l"(p));
    return v;
}
__device__ __forceinline__ void red_release_gpu_add1(unsigned* p) {
    asm volatile("red.release.gpu.global.add.u32 [%0], 1;" :: "l"(p) : "memory");
}
__device__ __forceinline__ void st_release_gpu(unsigned* p, unsigned v) {
    asm volatile("st.release.gpu.global.u32 [%0], %1;" :: "l"(p), "r"(v) : "memory");
}
// packed fp32 FMA: acc.{lo,hi} += a.{lo,hi} * b.{lo,hi}  (exact fp32, 2 lanes/inst)
__device__ __forceinline__ void fma2(unsigned long long& acc,
                                     unsigned long long a, unsigned long long b) {
    asm("fma.rn.f32x2 %0, %1, %2, %0;" : "+l"(acc) : "l"(a), "l"(b));
}
__device__ __forceinline__ float hsum2(unsigned long long v) {
    float lo, hi;
    asm("mov.b64 {%0, %1}, %2;" : "=f"(lo), "=f"(hi) : "l"(v));
    return lo + hi;
}

// gi[m,g] = sum_k X[m,k] * Wih[g,k] + bih[g];  M=32768, N=1024, K=512
__global__ __launch_bounds__(256) void gi_gemm(const float* __restrict__ X,
                                               const float* __restrict__ W,
                                               const float* __restrict__ bih) {
    __shared__ float As[32][68];
    __shared__ float Bs[32][68];
    const int m0 = blockIdx.y * 64;
    const int n0 = blockIdx.x * 64;
    const int tid = threadIdx.x;
    const int tx = tid & 15, ty = tid >> 4;
    const int lk = tid & 31, lr = tid >> 5;
    float acc[4][4] = {};
    for (int k0 = 0; k0 < IN_F; k0 += 32) {
        __syncthreads();
        #pragma unroll
        for (int i = 0; i < 8; i++) {
            As[lk][lr + 8 * i] = X[(size_t)(m0 + lr + 8 * i) * IN_F + k0 + lk];
            Bs[lk][lr + 8 * i] = W[(size_t)(n0 + lr + 8 * i) * IN_F + k0 + lk];
        }
        __syncthreads();
        #pragma unroll
        for (int kk = 0; kk < 32; kk++) {
            const float4 a = *(const float4*)&As[kk][4 * ty];
            const float4 b = *(const float4*)&Bs[kk][4 * tx];
            acc[0][0] += a.x * b.x; acc[0][1] += a.x * b.y; acc[0][2] += a.x * b.z; acc[0][3] += a.x * b.w;
            acc[1][0] += a.y * b.x; acc[1][1] += a.y * b.y; acc[1][2] += a.y * b.z; acc[1][3] += a.y * b.w;
            acc[2][0] += a.z * b.x; acc[2][1] += a.z * b.y; acc[2][2] += a.z * b.z; acc[2][3] += a.z * b.w;
            acc[3][0] += a.w * b.x; acc[3][1] += a.w * b.y; acc[3][2] += a.w * b.z; acc[3][3] += a.w * b.w;
        }
    }
    const float4 bv = *(const float4*)&bih[n0 + 4 * tx];
    #pragma unroll
    for (int i = 0; i < 4; i++) {
        float4 v;
        v.x = acc[i][0] + bv.x;
        v.y = acc[i][1] + bv.y;
        v.z = acc[i][2] + bv.z;
        v.w = acc[i][3] + bv.w;
        *(float4*)&g_gi[(size_t)(m0 + 4 * ty + i) * GATES + n0 + 4 * tx] = v;
    }
}

// Persistent recurrent scan: 128 CTAs x 512 threads. Each CTA owns 4 hidden
// columns; threads split K in half (half = tid>>8) and reduce via smem.
// Grid barrier: arrivals on a counter; CTA 0 alone polls it and fans the epoch
// out to 128 private flag lines; each CTA polls only its own flag line.
__global__ __launch_bounds__(SCAN_THREADS) void scan_kernel(const float* __restrict__ Whh,
                                                            const float* __restrict__ bhh,
                                                            float* __restrict__ out) {
    extern __shared__ float sm[];
    float*  Wf   = sm;                                   // [4][516]
    float*  Wn   = sm + 4 * WPADF;                       // [4][516]
    float4* hsm  = (float4*)(sm + SMEM_W_FLOATS);        // [64][129]
    float2* hred = (float2*)(sm + SMEM_W_FLOATS + SMEM_H_FLOAT4 * 4); // [64*4]

    const int tid  = threadIdx.x;
    const int jl   = tid & 3;
    const int b    = (tid >> 2) & 63;
    const int half = tid >> 8;            // 0 or 1: which 256-k slab
    const int j0   = blockIdx.x * 4;
    const int jg   = j0 + jl;
    const bool isCTA0 = (blockIdx.x == 0);

    // per-thread compute pointers (float4 / ulonglong2 views)
    const float4* hb  = hsm + b * HSTRIDE + half * 64;          // 64 float4 = 256 k
    const float4* wfq = (const float4*)(Wf + jl * WPADF) + half * 64;
    const float4* wnq = (const float4*)(Wn + jl * WPADF) + half * 64;

    // Stage this CTA's W_hh rows (f-gate rows jg, n-gate rows 512+jg)
    for (int i = tid; i < 4 * 512; i += SCAN_THREADS) {
        const int r = i >> 9, c = i & 511;
        Wf[r * WPADF + c] = Whh[(size_t)(j0 + r) * HID + c];
        Wn[r * WPADF + c] = Whh[(size_t)(HID + j0 + r) * HID + c];
    }
    const float bhf = bhh[jg];
    const float bhn = bhh[HID + jg];
    __syncthreads();

    // gi prefetch (gates are evaluated by half==0 threads only)
    float gif = 0.f, gin = 0.f;
    if (half == 0) {
        gif = g_gi[((size_t)b << 10) + jg];
        gin = g_gi[((size_t)b << 10) + HID + jg];
    }

    for (int t = 0; t < T_STEPS; t++) {
        if (t > 0) {
            __syncthreads();                         // all h(t-1) STGs issued
            if (tid == 0) red_release_gpu_add1(&g_bar);
            if (isCTA0 && tid < 32) {
                if (tid == 0) {
                    const unsigned target = (unsigned)SCAN_CTAS * (unsigned)t;
                    while (ld_acquire_gpu(&g_bar) < target) { }
                }
                __syncwarp();
                #pragma unroll
                for (int i = 0; i < 4; i++)
                    st_release_gpu(&g_flags[(tid + 32 * i) * 32], (unsigned)t);
            }
            if (tid == 0) {
                while (ld_acquire_gpu(&g_flags[blockIdx.x * 32]) < (unsigned)t) { }
            }
            __syncthreads();
        }

        // prefetch next step's gi (h-independent)
        float gif_n = 0.f, gin_n = 0.f;
        if (half == 0) {
            const int tn = (t + 1 < T_STEPS) ? (t + 1) : t;
            gif_n = g_gi[((size_t)tn << 16) + ((size_t)b << 10) + jg];
            gin_n = g_gi[((size_t)tn << 16) + ((size_t)b << 10) + HID + jg];
        }

        float accf = 0.f, accn = 0.f;
        if (t > 0) {
            const float* hbase = out + (size_t)(t - 1) * BATCH * HID;

            // stage full 64x512 h tile: 16 LDG.128/thread at high MLP, then STS
            float4 r[16];
            #pragma unroll
            for (int i = 0; i < 16; i++) {
                const int f = tid + SCAN_THREADS * i;        // float4 index
                r[i] = *(const float4*)(hbase + (f >> 7) * HID + 4 * (f & 127));
            }
            #pragma unroll
            for (int i = 0; i < 16; i++) {
                const int f = tid + SCAN_THREADS * i;
                hsm[(f >> 7) * HSTRIDE + (f & 127)] = r[i];
            }
            __syncthreads();

            // packed dual-lane inner product over this thread's 256 k
            unsigned long long af0 = 0ull, af1 = 0ull, an0 = 0ull, an1 = 0ull;
            #pragma unroll
            for (int q = 0; q < 64; q++) {
                const ulonglong2 h2  = *(const ulonglong2*)&hb[q];
                const ulonglong2 wf2 = *(const ulonglong2*)&wfq[q];
                const ulonglong2 wn2 = *(const ulonglong2*)&wnq[q];
                fma2(af0, h2.x, wf2.x);
                fma2(an0, h2.x, wn2.x);
                fma2(af1, h2.y, wf2.y);
                fma2(an1, h2.y, wn2.y);
            }
            accf = hsum2(af0) + hsum2(af1);
            accn = hsum2(an0) + hsum2(an1);

            // cross-half reduction
            if (half == 1) hred[b * 4 + jl] = make_float2(accf, accn);
            __syncthreads();
            if (half == 0) {
                const float2 o = hred[b * 4 + jl];
                accf += o.x;
                accn += o.y;
            }
        }

        // gates + write h_t (half==0 threads own the 256 (b,j) outputs)
        if (half == 0) {
            const float f  = 1.f / (1.f + expf(-(gif + accf + bhf)));
            const float hv = tanhf(gin + f * (accn + bhn));
            out[((size_t)t * BATCH + b) * HID + jg] = hv;
        }
        gif = gif_n;
        gin = gin_n;
    }

    // final arrival round: CTA0 resets counter+flags only after ALL finals,
    // so every CTA has passed every flag wait -> replay-safe, no deadlock.
    __syncthreads();
    if (tid == 0) red_release_gpu_add1(&g_bar);
    if (isCTA0 && tid < 32) {
        if (tid == 0) {
            while (ld_acquire_gpu(&g_bar) < (unsigned)SCAN_CTAS * (unsigned)T_STEPS) { }
        }
        __syncwarp();
        #pragma unroll
        for (int i = 0; i < 4; i++)
            *(volatile unsigned*)&g_flags[(tid + 32 * i) * 32] = 0u;
        if (tid == 0) *(volatile unsigned*)&g_bar = 0u;
    }
}

extern "C" void kernel_launch(void* const* d_in, const int* in_sizes, int n_in,
                              void* d_out, int out_size) {
    const float* X   = (const float*)d_in[0];  // (512, 64, 512)
    const float* Wih = (const float*)d_in[1];  // (1024, 512)
    const float* Whh = (const float*)d_in[2];  // (1024, 512)
    const float* bih = (const float*)d_in[3];  // (1024,)
    const float* bhh = (const float*)d_in[4];  // (1024,)
    float* out = (float*)d_out;                // (512, 64, 512)

    cudaFuncSetAttribute(scan_kernel,
                         cudaFuncAttributeMaxDynamicSharedMemorySize, SMEM_BYTES);

    dim3 g1(GATES / 64, (T_STEPS * BATCH) / 64);
    gi_gemm<<<g1, 256>>>(X, Wih, bih);
    scan_kernel<<<SCAN_CTAS, SCAN_THREADS, SMEM_BYTES>>>(Whh, bhh, out);
}

// round 7
// speedup vs baseline: 1.1316x; 1.1316x over previous
#include <cuda_runtime.h>
#include <math.h>

#define T_STEPS 512
#define BATCH   64
#define IN_F    512
#define HID     512
#define GATES   1024
#define SCAN_CTAS 128
#define SCAN_THREADS 512

#define WPADF   516                    // 512 + 4 floats pad (W rows, 16B-aligned stride)
#define HSTRIDE 129                    // h row stride in float4 (=516 floats)
#define SMEM_W_FLOATS (8 * WPADF)
#define SMEM_H_FLOAT4 (BATCH * HSTRIDE)
#define SMEM_RED_FLOATS (BATCH * 4 * 2)
#define SMEM_BYTES (SMEM_W_FLOATS * 4 + SMEM_H_FLOAT4 * 16 + SMEM_RED_FLOATS * 4)

// 128 MiB scratch for precomputed input gates gi[t][b][g]
__device__ float g_gi[(size_t)T_STEPS * BATCH * GATES];
__device__ unsigned int g_bar;   // zero at load; self-reset by last CTA each run

__device__ __forceinline__ unsigned ld_acquire_gpu(const unsigned* p) {
    unsigned v;
    asm volatile("ld.acquire.gpu.global.u32 %0, [%1];" : "=r"(v) : "l"(p));
    return v;
}
__device__ __forceinline__ void red_release_gpu_add1(unsigned* p) {
    asm volatile("red.release.gpu.global.add.u32 [%0], 1;" :: "l"(p) : "memory");
}
// packed fp32 FMA: acc.{lo,hi} += a.{lo,hi} * b.{lo,hi}  (exact fp32, 2 lanes/inst)
__device__ __forceinline__ void fma2(unsigned long long& acc,
                                     unsigned long long a, unsigned long long b) {
    asm("fma.rn.f32x2 %0, %1, %2, %0;" : "+l"(acc) : "l"(a), "l"(b));
}
__device__ __forceinline__ unsigned long long dup2(float a) {
    unsigned long long v;
    asm("mov.b64 %0, {%1, %1};" : "=l"(v) : "f"(a));
    return v;
}
__device__ __forceinline__ float hsum2(unsigned long long v) {
    float lo, hi;
    asm("mov.b64 {%0, %1}, %2;" : "=f"(lo), "=f"(hi) : "l"(v));
    return lo + hi;
}
__device__ __forceinline__ float2 unpack2(unsigned long long v) {
    float lo, hi;
    asm("mov.b64 {%0, %1}, %2;" : "=f"(lo), "=f"(hi) : "l"(v));
    return make_float2(lo, hi);
}

// gi[m,g] = sum_k X[m,k] * Wih[g,k] + bih[g];  M=32768, N=1024, K=512
// Inner loop uses fma.rn.f32x2 paired across adjacent n columns: the float4
// LDS of B yields two 64-bit lane pairs for free; A is lane-duplicated once.
__global__ __launch_bounds__(256) void gi_gemm(const float* __restrict__ X,
                                               const float* __restrict__ W,
                                               const float* __restrict__ bih) {
    __shared__ float As[32][68];
    __shared__ float Bs[32][68];
    const int m0 = blockIdx.y * 64;
    const int n0 = blockIdx.x * 64;
    const int tid = threadIdx.x;
    const int tx = tid & 15, ty = tid >> 4;
    const int lk = tid & 31, lr = tid >> 5;
    unsigned long long acc2[4][2] = {};   // [m-row][n-pair]
    for (int k0 = 0; k0 < IN_F; k0 += 32) {
        __syncthreads();
        #pragma unroll
        for (int i = 0; i < 8; i++) {
            As[lk][lr + 8 * i] = X[(size_t)(m0 + lr + 8 * i) * IN_F + k0 + lk];
            Bs[lk][lr + 8 * i] = W[(size_t)(n0 + lr + 8 * i) * IN_F + k0 + lk];
        }
        __syncthreads();
        #pragma unroll
        for (int kk = 0; kk < 32; kk++) {
            const float4 a = *(const float4*)&As[kk][4 * ty];
            const ulonglong2 b2 = *(const ulonglong2*)&Bs[kk][4 * tx];
            const unsigned long long a0 = dup2(a.x);
            const unsigned long long a1 = dup2(a.y);
            const unsigned long long a2 = dup2(a.z);
            const unsigned long long a3 = dup2(a.w);
            fma2(acc2[0][0], a0, b2.x); fma2(acc2[0][1], a0, b2.y);
            fma2(acc2[1][0], a1, b2.x); fma2(acc2[1][1], a1, b2.y);
            fma2(acc2[2][0], a2, b2.x); fma2(acc2[2][1], a2, b2.y);
            fma2(acc2[3][0], a3, b2.x); fma2(acc2[3][1], a3, b2.y);
        }
    }
    const float4 bv = *(const float4*)&bih[n0 + 4 * tx];
    #pragma unroll
    for (int i = 0; i < 4; i++) {
        const float2 c01 = unpack2(acc2[i][0]);
        const float2 c23 = unpack2(acc2[i][1]);
        float4 v;
        v.x = c01.x + bv.x;
        v.y = c01.y + bv.y;
        v.z = c23.x + bv.z;
        v.w = c23.y + bv.w;
        *(float4*)&g_gi[(size_t)(m0 + 4 * ty + i) * GATES + n0 + 4 * tx] = v;
    }
}

// Persistent recurrent scan: 128 CTAs x 512 threads. Each CTA owns 4 hidden
// columns; threads split K in half (half = tid>>8) and reduce via smem.
// Inner product uses packed fma.rn.f32x2 (2 k-lanes per instruction).
__global__ __launch_bounds__(SCAN_THREADS) void scan_kernel(const float* __restrict__ Whh,
                                                            const float* __restrict__ bhh,
                                                            float* __restrict__ out) {
    extern __shared__ float sm[];
    float*  Wf   = sm;                                   // [4][516]
    float*  Wn   = sm + 4 * WPADF;                       // [4][516]
    float4* hsm  = (float4*)(sm + SMEM_W_FLOATS);        // [64][129]
    float2* hred = (float2*)(sm + SMEM_W_FLOATS + SMEM_H_FLOAT4 * 4); // [64*4]

    const int tid  = threadIdx.x;
    const int jl   = tid & 3;
    const int b    = (tid >> 2) & 63;
    const int half = tid >> 8;            // 0 or 1: which 256-k slab
    const int j0   = blockIdx.x * 4;
    const int jg   = j0 + jl;

    // per-thread compute pointers (float4 / ulonglong2 views)
    const float4* hb  = hsm + b * HSTRIDE + half * 64;          // 64 float4 = 256 k
    const float4* wfq = (const float4*)(Wf + jl * WPADF) + half * 64;
    const float4* wnq = (const float4*)(Wn + jl * WPADF) + half * 64;

    // Stage this CTA's W_hh rows (f-gate rows jg, n-gate rows 512+jg)
    for (int i = tid; i < 4 * 512; i += SCAN_THREADS) {
        const int r = i >> 9, c = i & 511;
        Wf[r * WPADF + c] = Whh[(size_t)(j0 + r) * HID + c];
        Wn[r * WPADF + c] = Whh[(size_t)(HID + j0 + r) * HID + c];
    }
    const float bhf = bhh[jg];
    const float bhn = bhh[HID + jg];
    __syncthreads();

    // gi prefetch (gates are evaluated by half==0 threads only)
    float gif = 0.f, gin = 0.f;
    if (half == 0) {
        gif = g_gi[((size_t)b << 10) + jg];
        gin = g_gi[((size_t)b << 10) + HID + jg];
    }

    for (int t = 0; t < T_STEPS; t++) {
        if (t > 0) {
            // grid barrier: 1 arriver + 1 poller per CTA, acq/rel ordering
            __syncthreads();
            if (tid == 0) {
                red_release_gpu_add1(&g_bar);
                const unsigned target = (unsigned)SCAN_CTAS * (unsigned)t;
                while (ld_acquire_gpu(&g_bar) < target) __nanosleep(32);
            }
            __syncthreads();
        }

        // prefetch next step's gi (h-independent)
        float gif_n = 0.f, gin_n = 0.f;
        if (half == 0) {
            const int tn = (t + 1 < T_STEPS) ? (t + 1) : t;
            gif_n = g_gi[((size_t)tn << 16) + ((size_t)b << 10) + jg];
            gin_n = g_gi[((size_t)tn << 16) + ((size_t)b << 10) + HID + jg];
        }

        float accf = 0.f, accn = 0.f;
        if (t > 0) {
            const float* hbase = out + (size_t)(t - 1) * BATCH * HID;

            // stage full 64x512 h tile: 16 LDG.128/thread at high MLP, then STS
            float4 r[16];
            #pragma unroll
            for (int i = 0; i < 16; i++) {
                const int f = tid + SCAN_THREADS * i;        // float4 index
                r[i] = *(const float4*)(hbase + (f >> 7) * HID + 4 * (f & 127));
            }
            #pragma unroll
            for (int i = 0; i < 16; i++) {
                const int f = tid + SCAN_THREADS * i;
                hsm[(f >> 7) * HSTRIDE + (f & 127)] = r[i];
            }
            __syncthreads();

            // packed dual-lane inner product over this thread's 256 k
            unsigned long long af0 = 0ull, af1 = 0ull, an0 = 0ull, an1 = 0ull;
            #pragma unroll
            for (int q = 0; q < 64; q++) {
                const ulonglong2 h2  = *(const ulonglong2*)&hb[q];
                const ulonglong2 wf2 = *(const ulonglong2*)&wfq[q];
                const ulonglong2 wn2 = *(const ulonglong2*)&wnq[q];
                fma2(af0, h2.x, wf2.x);
                fma2(an0, h2.x, wn2.x);
                fma2(af1, h2.y, wf2.y);
                fma2(an1, h2.y, wn2.y);
            }
            accf = hsum2(af0) + hsum2(af1);
            accn = hsum2(an0) + hsum2(an1);

            // cross-half reduction
            if (half == 1) hred[b * 4 + jl] = make_float2(accf, accn);
            __syncthreads();
            if (half == 0) {
                const float2 o = hred[b * 4 + jl];
                accf += o.x;
                accn += o.y;
            }
        }

        // gates + write h_t (half==0 threads own the 256 (b,j) outputs)
        if (half == 0) {
            const float f  = 1.f / (1.f + expf(-(gif + accf + bhf)));
            const float hv = tanhf(gin + f * (accn + bhn));
            out[((size_t)t * BATCH + b) * HID + jg] = hv;
        }
        gif = gif_n;
        gin = gin_n;
    }

    // self-reset barrier for next graph replay: last arriving CTA clears it.
    __syncthreads();
    if (tid == 0) {
        const unsigned r = atomicAdd(&g_bar, 1u);
        if (r == (unsigned)SCAN_CTAS * (unsigned)T_STEPS - 1u)
            *((volatile unsigned*)&g_bar) = 0u;
    }
}

extern "C" void kernel_launch(void* const* d_in, const int* in_sizes, int n_in,
                              void* d_out, int out_size) {
    const float* X   = (const float*)d_in[0];  // (512, 64, 512)
    const float* Wih = (const float*)d_in[1];  // (1024, 512)
    const float* Whh = (const float*)d_in[2];  // (1024, 512)
    const float* bih = (const float*)d_in[3];  // (1024,)
    const float* bhh = (const float*)d_in[4];  // (1024,)
    float* out = (float*)d_out;                // (512, 64, 512)

    cudaFuncSetAttribute(scan_kernel,
                         cudaFuncAttributeMaxDynamicSharedMemorySize, SMEM_BYTES);

    dim3 g1(GATES / 64, (T_STEPS * BATCH) / 64);
    gi_gemm<<<g1, 256>>>(X, Wih, bih);
    scan_kernel<<<SCAN_CTAS, SCAN_THREADS, SMEM_BYTES>>>(Whh, bhh, out);
}

// round 9
// speedup vs baseline: 1.2021x; 1.0623x over previous
#include <cuda_runtime.h>
#include <cstdint>
#include <math.h>

#define T_STEPS 512
#define BATCH   64
#define IN_F    512
#define HID     512
#define GATES   1024
#define SCAN_CTAS 128
#define SCAN_THREADS 512

#define WPADF   516
#define HSTRIDE 129
#define SMEM_W_FLOATS (8 * WPADF)
#define SMEM_H_FLOAT4 (BATCH * HSTRIDE)
#define SMEM_RED_FLOATS (BATCH * 4 * 2)
#define SMEM_BYTES (SMEM_W_FLOATS * 4 + SMEM_H_FLOAT4 * 16 + SMEM_RED_FLOATS * 4)

// gi tensor-core GEMM tiling
#define GI_KC    32                    // k per stage chunk
#define GSTRIDE  36                    // padded row stride (floats) - ldmatrix conflict-free
#define GI_SMEM_BYTES (4 * 128 * GSTRIDE * 4)   // Ahi|Alo|Bhi|Blo

// 128 MiB scratch for precomputed input gates gi[t][b][g]
__device__ float g_gi[(size_t)T_STEPS * BATCH * GATES];
__device__ unsigned int g_bar;   // zero at load; self-reset by last CTA each run

__device__ __forceinline__ unsigned ld_acquire_gpu(const unsigned* p) {
    unsigned v;
    asm volatile("ld.acquire.gpu.global.u32 %0, [%1];" : "=r"(v) : "l"(p));
    return v;
}
__device__ __forceinline__ void red_release_gpu_add1(unsigned* p) {
    asm volatile("red.release.gpu.global.add.u32 [%0], 1;" :: "l"(p) : "memory");
}
__device__ __forceinline__ void fma2(unsigned long long& acc,
                                     unsigned long long a, unsigned long long b) {
    asm("fma.rn.f32x2 %0, %1, %2, %0;" : "+l"(acc) : "l"(a), "l"(b));
}
__device__ __forceinline__ float hsum2(unsigned long long v) {
    float lo, hi;
    asm("mov.b64 {%0, %1}, %2;" : "=f"(lo), "=f"(hi) : "l"(v));
    return lo + hi;
}

// ---- tf32 MMA helpers ----
__device__ __forceinline__ unsigned f2tf32(float x) {
    unsigned r;
    asm("cvt.rna.tf32.f32 %0, %1;" : "=r"(r) : "f"(x));
    return r;
}
__device__ __forceinline__ void cvt_split(float x, unsigned& hi, unsigned& lo) {
    hi = f2tf32(x);
    lo = f2tf32(x - __uint_as_float(hi));
}
__device__ __forceinline__ uint32_t smem_u32(const void* p) {
    uint32_t a;
    asm("{.reg .u64 t; cvta.to.shared.u64 t, %1; cvt.u32.u64 %0, t;}" : "=r"(a) : "l"(p));
    return a;
}
__device__ __forceinline__ void ldsm4(unsigned* r, uint32_t addr) {
    asm volatile("ldmatrix.sync.aligned.m8n8.x4.shared.b16 {%0,%1,%2,%3}, [%4];"
                 : "=r"(r[0]), "=r"(r[1]), "=r"(r[2]), "=r"(r[3]) : "r"(addr));
}
__device__ __forceinline__ void mma_tf32(float* c, const unsigned* a, const unsigned* b) {
    asm volatile("mma.sync.aligned.m16n8k8.row.col.f32.tf32.tf32.f32 "
                 "{%0,%1,%2,%3}, {%4,%5,%6,%7}, {%8,%9}, {%0,%1,%2,%3};"
                 : "+f"(c[0]), "+f"(c[1]), "+f"(c[2]), "+f"(c[3])
                 : "r"(a[0]), "r"(a[1]), "r"(a[2]), "r"(a[3]), "r"(b[0]), "r"(b[1]));
}

// gi[m,g] = sum_k X[m,k]*Wih[g,k] + bih[g]  via split-tf32 (3-pass) tensor MMA.
// CTA tile 128x128, 16 warps of 32x32, K chunked by 32 and staged as tf32 hi/lo.
__global__ __launch_bounds__(512) void gi_gemm_mma(const float* __restrict__ X,
                                                   const float* __restrict__ W,
                                                   const float* __restrict__ bih) {
    extern __shared__ unsigned gsm[];
    unsigned* Ahi = gsm;
    unsigned* Alo = gsm + 128 * GSTRIDE;
    unsigned* Bhi = gsm + 2 * 128 * GSTRIDE;
    unsigned* Blo = gsm + 3 * 128 * GSTRIDE;

    const int tid  = threadIdx.x;
    const int lane = tid & 31;
    const int wid  = tid >> 5;
    const int warpM = (wid & 3) * 32;    // within-CTA
    const int warpN = (wid >> 2) * 32;
    const int Mb = blockIdx.y * 128;
    const int Nb = blockIdx.x * 128;

    // ldmatrix lane address components (constant across chunks)
    const int aRow = warpM + (lane & 15);
    const int aColOff = (lane >> 4) << 2;
    const int bRow = warpN + ((lane >> 4) << 3) + (lane & 7);
    const int bColOff = ((lane >> 3) & 1) << 2;

    float acc[2][4][4];
    #pragma unroll
    for (int mt = 0; mt < 2; mt++)
        #pragma unroll
        for (int nt = 0; nt < 4; nt++)
            #pragma unroll
            for (int i = 0; i < 4; i++) acc[mt][nt][i] = 0.f;

    const int srow = tid >> 3;           // 0..63
    const int sc4  = (tid & 7) * 4;      // 0..28

    for (int k0 = 0; k0 < IN_F; k0 += GI_KC) {
        __syncthreads();
        // stage + convert: A rows Mb+0..127, B rows Nb+0..127, cols k0..k0+31
        #pragma unroll
        for (int i = 0; i < 2; i++) {
            const int row = srow + 64 * i;
            const float4 a = *(const float4*)&X[(size_t)(Mb + row) * IN_F + k0 + sc4];
            const float4 b = *(const float4*)&W[(size_t)(Nb + row) * IN_F + k0 + sc4];
            uint4 ah, al, bh, bl;
            cvt_split(a.x, ah.x, al.x); cvt_split(a.y, ah.y, al.y);
            cvt_split(a.z, ah.z, al.z); cvt_split(a.w, ah.w, al.w);
            cvt_split(b.x, bh.x, bl.x); cvt_split(b.y, bh.y, bl.y);
            cvt_split(b.z, bh.z, bl.z); cvt_split(b.w, bh.w, bl.w);
            const int off = row * GSTRIDE + sc4;
            *(uint4*)&Ahi[off] = ah;
            *(uint4*)&Alo[off] = al;
            *(uint4*)&Bhi[off] = bh;
            *(uint4*)&Blo[off] = bl;
        }
        __syncthreads();

        #pragma unroll
        for (int k8 = 0; k8 < GI_KC / 8; k8++) {
            const int kb = k8 * 8;
            unsigned ah[2][4], al[2][4], bh[4][2], bl[4][2];
            #pragma unroll
            for (int mt = 0; mt < 2; mt++) {
                const int off = (aRow + mt * 16) * GSTRIDE + kb + aColOff;
                ldsm4(ah[mt], smem_u32(&Ahi[off]));
                ldsm4(al[mt], smem_u32(&Alo[off]));
            }
            #pragma unroll
            for (int np = 0; np < 2; np++) {
                const int off = (bRow + np * 16) * GSTRIDE + kb + bColOff;
                unsigned r[4];
                ldsm4(r, smem_u32(&Bhi[off]));
                bh[2 * np][0] = r[0]; bh[2 * np][1] = r[1];
                bh[2 * np + 1][0] = r[2]; bh[2 * np + 1][1] = r[3];
                ldsm4(r, smem_u32(&Blo[off]));
                bl[2 * np][0] = r[0]; bl[2 * np][1] = r[1];
                bl[2 * np + 1][0] = r[2]; bl[2 * np + 1][1] = r[3];
            }
            #pragma unroll
            for (int mt = 0; mt < 2; mt++)
                #pragma unroll
                for (int nt = 0; nt < 4; nt++) {
                    mma_tf32(acc[mt][nt], ah[mt], bh[nt]);   // hi*hi
                    mma_tf32(acc[mt][nt], ah[mt], bl[nt]);   // hi*lo
                    mma_tf32(acc[mt][nt], al[mt], bh[nt]);   // lo*hi
                }
        }
    }

    // epilogue: C frag (c0,c1)=(row, 2q..2q+1), (c2,c3)=(row+8, ...)
    #pragma unroll
    for (int mt = 0; mt < 2; mt++)
        #pragma unroll
        for (int nt = 0; nt < 4; nt++) {
            const int gr = Mb + warpM + mt * 16 + (lane >> 2);
            const int gc = Nb + warpN + nt * 8 + 2 * (lane & 3);
            const float2 bv = *(const float2*)&bih[gc];
            float2 v0, v1;
            v0.x = acc[mt][nt][0] + bv.x; v0.y = acc[mt][nt][1] + bv.y;
            v1.x = acc[mt][nt][2] + bv.x; v1.y = acc[mt][nt][3] + bv.y;
            *(float2*)&g_gi[(size_t)gr * GATES + gc] = v0;
            *(float2*)&g_gi[(size_t)(gr + 8) * GATES + gc] = v1;
        }
}

// Persistent recurrent scan: unchanged from best-measured version (R5/R7).
__global__ __launch_bounds__(SCAN_THREADS) void scan_kernel(const float* __restrict__ Whh,
                                                            const float* __restrict__ bhh,
                                                            float* __restrict__ out) {
    extern __shared__ float sm[];
    float*  Wf   = sm;
    float*  Wn   = sm + 4 * WPADF;
    float4* hsm  = (float4*)(sm + SMEM_W_FLOATS);
    float2* hred = (float2*)(sm + SMEM_W_FLOATS + SMEM_H_FLOAT4 * 4);

    const int tid  = threadIdx.x;
    const int jl   = tid & 3;
    const int b    = (tid >> 2) & 63;
    const int half = tid >> 8;
    const int j0   = blockIdx.x * 4;
    const int jg   = j0 + jl;

    const float4* hb  = hsm + b * HSTRIDE + half * 64;
    const float4* wfq = (const float4*)(Wf + jl * WPADF) + half * 64;
    const float4* wnq = (const float4*)(Wn + jl * WPADF) + half * 64;

    for (int i = tid; i < 4 * 512; i += SCAN_THREADS) {
        const int r = i >> 9, c = i & 511;
        Wf[r * WPADF + c] = Whh[(size_t)(j0 + r) * HID + c];
        Wn[r * WPADF + c] = Whh[(size_t)(HID + j0 + r) * HID + c];
    }
    const float bhf = bhh[jg];
    const float bhn = bhh[HID + jg];
    __syncthreads();

    float gif = 0.f, gin = 0.f;
    if (half == 0) {
        gif = g_gi[((size_t)b << 10) + jg];
        gin = g_gi[((size_t)b << 10) + HID + jg];
    }

    for (int t = 0; t < T_STEPS; t++) {
        if (t > 0) {
            __syncthreads();
            if (tid == 0) {
                red_release_gpu_add1(&g_bar);
                const unsigned target = (unsigned)SCAN_CTAS * (unsigned)t;
                while (ld_acquire_gpu(&g_bar) < target) __nanosleep(32);
            }
            __syncthreads();
        }

        float gif_n = 0.f, gin_n = 0.f;
        if (half == 0) {
            const int tn = (t + 1 < T_STEPS) ? (t + 1) : t;
            gif_n = g_gi[((size_t)tn << 16) + ((size_t)b << 10) + jg];
            gin_n = g_gi[((size_t)tn << 16) + ((size_t)b << 10) + HID + jg];
        }

        float accf = 0.f, accn = 0.f;
        if (t > 0) {
            const float* hbase = out + (size_t)(t - 1) * BATCH * HID;

            float4 r[16];
            #pragma unroll
            for (int i = 0; i < 16; i++) {
                const int f = tid + SCAN_THREADS * i;
                r[i] = *(const float4*)(hbase + (f >> 7) * HID + 4 * (f & 127));
            }
            #pragma unroll
            for (int i = 0; i < 16; i++) {
                const int f = tid + SCAN_THREADS * i;
                hsm[(f >> 7) * HSTRIDE + (f & 127)] = r[i];
            }
            __syncthreads();

            unsigned long long af0 = 0ull, af1 = 0ull, an0 = 0ull, an1 = 0ull;
            #pragma unroll
            for (int q = 0; q < 64; q++) {
                const ulonglong2 h2  = *(const ulonglong2*)&hb[q];
                const ulonglong2 wf2 = *(const ulonglong2*)&wfq[q];
                const ulonglong2 wn2 = *(const ulonglong2*)&wnq[q];
                fma2(af0, h2.x, wf2.x);
                fma2(an0, h2.x, wn2.x);
                fma2(af1, h2.y, wf2.y);
                fma2(an1, h2.y, wn2.y);
            }
            accf = hsum2(af0) + hsum2(af1);
            accn = hsum2(an0) + hsum2(an1);

            if (half == 1) hred[b * 4 + jl] = make_float2(accf, accn);
            __syncthreads();
            if (half == 0) {
                const float2 o = hred[b * 4 + jl];
                accf += o.x;
                accn += o.y;
            }
        }

        if (half == 0) {
            const float f  = 1.f / (1.f + expf(-(gif + accf + bhf)));
            const float hv = tanhf(gin + f * (accn + bhn));
            out[((size_t)t * BATCH + b) * HID + jg] = hv;
        }
        gif = gif_n;
        gin = gin_n;
    }

    __syncthreads();
    if (tid == 0) {
        const unsigned r = atomicAdd(&g_bar, 1u);
        if (r == (unsigned)SCAN_CTAS * (unsigned)T_STEPS - 1u)
            *((volatile unsigned*)&g_bar) = 0u;
    }
}

extern "C" void kernel_launch(void* const* d_in, const int* in_sizes, int n_in,
                              void* d_out, int out_size) {
    const float* X   = (const float*)d_in[0];  // (512, 64, 512)
    const float* Wih = (const float*)d_in[1];  // (1024, 512)
    const float* Whh = (const float*)d_in[2];  // (1024, 512)
    const float* bih = (const float*)d_in[3];  // (1024,)
    const float* bhh = (const float*)d_in[4];  // (1024,)
    float* out = (float*)d_out;                // (512, 64, 512)

    cudaFuncSetAttribute(gi_gemm_mma,
                         cudaFuncAttributeMaxDynamicSharedMemorySize, GI_SMEM_BYTES);
    cudaFuncSetAttribute(scan_kernel,
                         cudaFuncAttributeMaxDynamicSharedMemorySize, SMEM_BYTES);

    dim3 g1(GATES / 128, (T_STEPS * BATCH) / 128);
    gi_gemm_mma<<<g1, 512, GI_SMEM_BYTES>>>(X, Wih, bih);
    scan_kernel<<<SCAN_CTAS, SCAN_THREADS, SMEM_BYTES>>>(Whh, bhh, out);
}

// round 10
// speedup vs baseline: 1.8858x; 1.5687x over previous
#include <cuda_runtime.h>
#include <cuda_bf16.h>
#include <cstdint>
#include <math.h>

#define T_STEPS 512
#define BATCH   64
#define IN_F    512
#define HID     512
#define GATES   1024
#define SCAN_CTAS 128

// gi tensor-core GEMM tiling (unchanged, verified R9)
#define GI_KC    32
#define GSTRIDE  36
#define GI_SMEM_BYTES (4 * 128 * GSTRIDE * 4)

// scan smem layout (bytes)
#define HROW        520                          // bf16 row stride: 1040B, 65x16B -> conflict-free
#define PLANE_BYTES (BATCH * HROW * 2)           // 66560
#define RED_OFF     (2 * PLANE_BYTES)            // 133120
#define SCAN_SMEM_BYTES (RED_OFF + 4 * 64 * 8 * 4)   // +8KB reduction = 141312

// scratch: input gates + per-step bf16 hi/lo h planes
__device__ float g_gi[(size_t)T_STEPS * BATCH * GATES];
__device__ unsigned short g_hhi[(size_t)T_STEPS * BATCH * HID];
__device__ unsigned short g_hlo[(size_t)T_STEPS * BATCH * HID];
__device__ unsigned int g_bar;   // zero at load; self-reset by last CTA each run

__device__ __forceinline__ unsigned ld_acquire_gpu(const unsigned* p) {
    unsigned v;
    asm volatile("ld.acquire.gpu.global.u32 %0, [%1];" : "=r"(v) : "l"(p));
    return v;
}
__device__ __forceinline__ void red_release_gpu_add1(unsigned* p) {
    asm volatile("red.release.gpu.global.add.u32 [%0], 1;" :: "l"(p) : "memory");
}

// ---- tf32 helpers (gi GEMM, verified) ----
__device__ __forceinline__ unsigned f2tf32(float x) {
    unsigned r;
    asm("cvt.rna.tf32.f32 %0, %1;" : "=r"(r) : "f"(x));
    return r;
}
__device__ __forceinline__ void cvt_split(float x, unsigned& hi, unsigned& lo) {
    hi = f2tf32(x);
    lo = f2tf32(x - __uint_as_float(hi));
}
__device__ __forceinline__ uint32_t smem_u32(const void* p) {
    uint32_t a;
    asm("{.reg .u64 t; cvta.to.shared.u64 t, %1; cvt.u32.u64 %0, t;}" : "=r"(a) : "l"(p));
    return a;
}
__device__ __forceinline__ void ldsm4(unsigned* r, uint32_t addr) {
    asm volatile("ldmatrix.sync.aligned.m8n8.x4.shared.b16 {%0,%1,%2,%3}, [%4];"
                 : "=r"(r[0]), "=r"(r[1]), "=r"(r[2]), "=r"(r[3]) : "r"(addr));
}
__device__ __forceinline__ void ldsm2(unsigned* r, uint32_t addr) {
    asm volatile("ldmatrix.sync.aligned.m8n8.x2.shared.b16 {%0,%1}, [%2];"
                 : "=r"(r[0]), "=r"(r[1]) : "r"(addr));
}
__device__ __forceinline__ void mma_tf32(float* c, const unsigned* a, const unsigned* b) {
    asm volatile("mma.sync.aligned.m16n8k8.row.col.f32.tf32.tf32.f32 "
                 "{%0,%1,%2,%3}, {%4,%5,%6,%7}, {%8,%9}, {%0,%1,%2,%3};"
                 : "+f"(c[0]), "+f"(c[1]), "+f"(c[2]), "+f"(c[3])
                 : "r"(a[0]), "r"(a[1]), "r"(a[2]), "r"(a[3]), "r"(b[0]), "r"(b[1]));
}
__device__ __forceinline__ void mma_bf16(float* c, const unsigned* a, const unsigned* b) {
    asm volatile("mma.sync.aligned.m16n8k16.row.col.f32.bf16.bf16.f32 "
                 "{%0,%1,%2,%3}, {%4,%5,%6,%7}, {%8,%9}, {%0,%1,%2,%3};"
                 : "+f"(c[0]), "+f"(c[1]), "+f"(c[2]), "+f"(c[3])
                 : "r"(a[0]), "r"(a[1]), "r"(a[2]), "r"(a[3]), "r"(b[0]), "r"(b[1]));
}
__device__ __forceinline__ void cp_async16(uint32_t smem, const void* gptr) {
    asm volatile("cp.async.cg.shared.global [%0], [%1], 16;" :: "r"(smem), "l"(gptr) : "memory");
}
__device__ __forceinline__ void cp_commit_wait() {
    asm volatile("cp.async.commit_group;\ncp.async.wait_group 0;" ::: "memory");
}

// ===================== gi GEMM (unchanged from R9) =====================
__global__ __launch_bounds__(512) void gi_gemm_mma(const float* __restrict__ X,
                                                   const float* __restrict__ W,
                                                   const float* __restrict__ bih) {
    extern __shared__ unsigned gsm[];
    unsigned* Ahi = gsm;
    unsigned* Alo = gsm + 128 * GSTRIDE;
    unsigned* Bhi = gsm + 2 * 128 * GSTRIDE;
    unsigned* Blo = gsm + 3 * 128 * GSTRIDE;

    const int tid  = threadIdx.x;
    const int lane = tid & 31;
    const int wid  = tid >> 5;
    const int warpM = (wid & 3) * 32;
    const int warpN = (wid >> 2) * 32;
    const int Mb = blockIdx.y * 128;
    const int Nb = blockIdx.x * 128;

    const int aRow = warpM + (lane & 15);
    const int aColOff = (lane >> 4) << 2;
    const int bRow = warpN + ((lane >> 4) << 3) + (lane & 7);
    const int bColOff = ((lane >> 3) & 1) << 2;

    float acc[2][4][4];
    #pragma unroll
    for (int mt = 0; mt < 2; mt++)
        #pragma unroll
        for (int nt = 0; nt < 4; nt++)
            #pragma unroll
            for (int i = 0; i < 4; i++) acc[mt][nt][i] = 0.f;

    const int srow = tid >> 3;
    const int sc4  = (tid & 7) * 4;

    for (int k0 = 0; k0 < IN_F; k0 += GI_KC) {
        __syncthreads();
        #pragma unroll
        for (int i = 0; i < 2; i++) {
            const int row = srow + 64 * i;
            const float4 a = *(const float4*)&X[(size_t)(Mb + row) * IN_F + k0 + sc4];
            const float4 b = *(const float4*)&W[(size_t)(Nb + row) * IN_F + k0 + sc4];
            uint4 ah, al, bh, bl;
            cvt_split(a.x, ah.x, al.x); cvt_split(a.y, ah.y, al.y);
            cvt_split(a.z, ah.z, al.z); cvt_split(a.w, ah.w, al.w);
            cvt_split(b.x, bh.x, bl.x); cvt_split(b.y, bh.y, bl.y);
            cvt_split(b.z, bh.z, bl.z); cvt_split(b.w, bh.w, bl.w);
            const int off = row * GSTRIDE + sc4;
            *(uint4*)&Ahi[off] = ah;
            *(uint4*)&Alo[off] = al;
            *(uint4*)&Bhi[off] = bh;
            *(uint4*)&Blo[off] = bl;
        }
        __syncthreads();

        #pragma unroll
        for (int k8 = 0; k8 < GI_KC / 8; k8++) {
            const int kb = k8 * 8;
            unsigned ah[2][4], al[2][4], bh[4][2], bl[4][2];
            #pragma unroll
            for (int mt = 0; mt < 2; mt++) {
                const int off = (aRow + mt * 16) * GSTRIDE + kb + aColOff;
                ldsm4(ah[mt], smem_u32(&Ahi[off]));
                ldsm4(al[mt], smem_u32(&Alo[off]));
            }
            #pragma unroll
            for (int np = 0; np < 2; np++) {
                const int off = (bRow + np * 16) * GSTRIDE + kb + bColOff;
                unsigned r[4];
                ldsm4(r, smem_u32(&Bhi[off]));
                bh[2 * np][0] = r[0]; bh[2 * np][1] = r[1];
                bh[2 * np + 1][0] = r[2]; bh[2 * np + 1][1] = r[3];
                ldsm4(r, smem_u32(&Blo[off]));
                bl[2 * np][0] = r[0]; bl[2 * np][1] = r[1];
                bl[2 * np + 1][0] = r[2]; bl[2 * np + 1][1] = r[3];
            }
            #pragma unroll
            for (int mt = 0; mt < 2; mt++)
                #pragma unroll
                for (int nt = 0; nt < 4; nt++) {
                    mma_tf32(acc[mt][nt], ah[mt], bh[nt]);
                    mma_tf32(acc[mt][nt], ah[mt], bl[nt]);
                    mma_tf32(acc[mt][nt], al[mt], bh[nt]);
                }
        }
    }

    #pragma unroll
    for (int mt = 0; mt < 2; mt++)
        #pragma unroll
        for (int nt = 0; nt < 4; nt++) {
            const int gr = Mb + warpM + mt * 16 + (lane >> 2);
            const int gc = Nb + warpN + nt * 8 + 2 * (lane & 3);
            const float2 bv = *(const float2*)&bih[gc];
            float2 v0, v1;
            v0.x = acc[mt][nt][0] + bv.x; v0.y = acc[mt][nt][1] + bv.y;
            v1.x = acc[mt][nt][2] + bv.x; v1.y = acc[mt][nt][3] + bv.y;
            *(float2*)&g_gi[(size_t)gr * GATES + gc] = v0;
            *(float2*)&g_gi[(size_t)(gr + 8) * GATES + gc] = v1;
        }
}

// ===================== tensor-core recurrent scan =====================
// 128 CTAs x 512 threads (16 warps = 4 M-tiles x 4 K-slices). Each CTA owns
// 8 gate rows (4 f + 4 n). W fragments (split-bf16) are register-resident for
// all steps; h is produced as bf16 hi/lo planes per step, staged via
// cp.async.cg, consumed via ldmatrix + mma.m16n8k16 (3-pass split-bf16).
__global__ __launch_bounds__(512) void scan_kernel(const float* __restrict__ Whh,
                                                   const float* __restrict__ bhh,
                                                   float* __restrict__ out) {
    extern __shared__ unsigned char smraw[];
    unsigned short* hhi = (unsigned short*)smraw;                 // [64][520]
    unsigned short* hlo = (unsigned short*)(smraw + PLANE_BYTES); // [64][520]
    float* red = (float*)(smraw + RED_OFF);                       // [4][64][8]

    const int tid  = threadIdx.x;
    const int lane = tid & 31;
    const int wid  = tid >> 5;
    const int mt   = wid & 3;           // M tile (16 rows of b)
    const int ksl  = wid >> 2;          // K slice (128 k)
    const int j0   = blockIdx.x * 4;

    // ---- one-time: stage W rows as bf16 hi/lo, load B frags into registers ----
    unsigned short* Whi_s = hhi;                 // overlay (freed before step loop)
    unsigned short* Wlo_s = hhi + 8 * HROW;
    for (int i = tid; i < 8 * 512; i += 512) {
        const int n = i >> 9, c = i & 511;
        const int gr = (n < 4) ? (j0 + n) : (HID + j0 + (n - 4));
        const float w = Whh[(size_t)gr * HID + c];
        const __nv_bfloat16 h16 = __float2bfloat16(w);
        const __nv_bfloat16 l16 = __float2bfloat16(w - __bfloat162float(h16));
        Whi_s[n * HROW + c] = __bfloat16_as_ushort(h16);
        Wlo_s[n * HROW + c] = __bfloat16_as_ushort(l16);
    }
    __syncthreads();
    unsigned wbh[8][2], wbl[8][2];
    {
        const int brow = lane & 7;
        const int bcol = ((lane >> 3) & 1) * 8;
        #pragma unroll
        for (int s = 0; s < 8; s++) {
            const int k0 = ksl * 128 + s * 16;
            ldsm2(wbh[s], smem_u32(&Whi_s[brow * HROW + k0 + bcol]));
            ldsm2(wbl[s], smem_u32(&Wlo_s[brow * HROW + k0 + bcol]));
        }
    }
    __syncthreads();   // W smem region now reusable for h planes

    // A-frag ldmatrix row (constant): rows m0..m0+15, col groups of 8
    const int arow  = mt * 16 + (lane & 7) + 8 * ((lane >> 3) & 1);
    const int acol8 = (lane >> 4) * 8;
    const uint32_t ahi_base = smem_u32(&hhi[arow * HROW]);
    const uint32_t alo_base = smem_u32(&hlo[arow * HROW]);

    // gate-thread constants (tid < 256): jl = tid&3, b = tid>>2
    const int jl = tid & 3;
    const int b  = tid >> 2;
    const int jg = j0 + jl;
    float bhf = 0.f, bhn = 0.f, gif = 0.f, gin = 0.f;
    if (tid < 256) {
        bhf = bhh[jg];
        bhn = bhh[HID + jg];
        gif = g_gi[((size_t)b << 10) + jg];
        gin = g_gi[((size_t)b << 10) + HID + jg];
    }

    for (int t = 0; t < T_STEPS; t++) {
        if (t > 0) {
            // grid barrier: 1 arriver + 1 poller per CTA (flat counter, R5-best)
            __syncthreads();
            if (tid == 0) {
                red_release_gpu_add1(&g_bar);
                const unsigned target = (unsigned)SCAN_CTAS * (unsigned)t;
                while (ld_acquire_gpu(&g_bar) < target) __nanosleep(32);
            }
            __syncthreads();
        }

        // prefetch next step's gi (h-independent)
        float gif_n = 0.f, gin_n = 0.f;
        if (tid < 256) {
            const int tn = (t + 1 < T_STEPS) ? (t + 1) : t;
            gif_n = g_gi[((size_t)tn << 16) + ((size_t)b << 10) + jg];
            gin_n = g_gi[((size_t)tn << 16) + ((size_t)b << 10) + HID + jg];
        }

        float accf = 0.f, accn = 0.f;
        if (t > 0) {
            // ---- stage h(t-1) bf16 planes into smem (L1-bypassing 16B copies) ----
            const unsigned short* ph = g_hhi + (size_t)(t - 1) * BATCH * HID;
            const unsigned short* pl = g_hlo + (size_t)(t - 1) * BATCH * HID;
            #pragma unroll
            for (int i = 0; i < 8; i++) {
                const int idx = tid + 512 * i;          // 16B chunk index
                const int br = idx >> 6, c = idx & 63;
                cp_async16(smem_u32(&hhi[br * HROW + c * 8]), ph + idx * 8);
                cp_async16(smem_u32(&hlo[br * HROW + c * 8]), pl + idx * 8);
            }
            cp_commit_wait();
            __syncthreads();

            // ---- split-bf16 MMA: D[64x8] partial over this warp's 128 k ----
            float c4[4] = {0.f, 0.f, 0.f, 0.f};
            #pragma unroll
            for (int s = 0; s < 8; s++) {
                const int k0 = ksl * 128 + s * 16;
                unsigned ah[4], al[4];
                ldsm4(ah, ahi_base + (k0 + acol8) * 2);
                ldsm4(al, alo_base + (k0 + acol8) * 2);
                mma_bf16(c4, ah, wbh[s]);   // hi*hi
                mma_bf16(c4, ah, wbl[s]);   // hi*lo
                mma_bf16(c4, al, wbh[s]);   // lo*hi
            }
            // partials -> red[ksl][m][n]
            const int rm = mt * 16 + (lane >> 2);
            const int rn = 2 * (lane & 3);
            *(float2*)&red[ksl * 512 + rm * 8 + rn] = make_float2(c4[0], c4[1]);
            *(float2*)&red[ksl * 512 + (rm + 8) * 8 + rn] = make_float2(c4[2], c4[3]);
            __syncthreads();

            if (tid < 256) {
                #pragma unroll
                for (int k = 0; k < 4; k++) {
                    accf += red[k * 512 + b * 8 + jl];
                    accn += red[k * 512 + b * 8 + 4 + jl];
                }
            }
        }

        // gates + write h_t (fp32 out + bf16 hi/lo planes)
        if (tid < 256) {
            const float f  = 1.f / (1.f + expf(-(gif + accf + bhf)));
            const float hv = tanhf(gin + f * (accn + bhn));
            out[((size_t)t * BATCH + b) * HID + jg] = hv;
            const __nv_bfloat16 h16 = __float2bfloat16(hv);
            const __nv_bfloat16 l16 = __float2bfloat16(hv - __bfloat162float(h16));
            g_hhi[(size_t)t * BATCH * HID + b * HID + jg] = __bfloat16_as_ushort(h16);
            g_hlo[(size_t)t * BATCH * HID + b * HID + jg] = __bfloat16_as_ushort(l16);
        }
        gif = gif_n;
        gin = gin_n;
    }

    // self-reset barrier for next graph replay: last arriving CTA clears it.
    __syncthreads();
    if (tid == 0) {
        const unsigned r = atomicAdd(&g_bar, 1u);
        if (r == (unsigned)SCAN_CTAS * (unsigned)T_STEPS - 1u)
            *((volatile unsigned*)&g_bar) = 0u;
    }
}

extern "C" void kernel_launch(void* const* d_in, const int* in_sizes, int n_in,
                              void* d_out, int out_size) {
    const float* X   = (const float*)d_in[0];  // (512, 64, 512)
    const float* Wih = (const float*)d_in[1];  // (1024, 512)
    const float* Whh = (const float*)d_in[2];  // (1024, 512)
    const float* bih = (const float*)d_in[3];  // (1024,)
    const float* bhh = (const float*)d_in[4];  // (1024,)
    float* out = (float*)d_out;                // (512, 64, 512)

    cudaFuncSetAttribute(gi_gemm_mma,
                         cudaFuncAttributeMaxDynamicSharedMemorySize, GI_SMEM_BYTES);
    cudaFuncSetAttribute(scan_kernel,
                         cudaFuncAttributeMaxDynamicSharedMemorySize, SCAN_SMEM_BYTES);

    dim3 g1(GATES / 128, (T_STEPS * BATCH) / 128);
    gi_gemm_mma<<<g1, 512, GI_SMEM_BYTES>>>(X, Wih, bih);
    scan_kernel<<<SCAN_CTAS, 512, SCAN_SMEM_BYTES>>>(Whh, bhh, out);
}

// round 11
// speedup vs baseline: 2.0622x; 1.0936x over previous
#include <cuda_runtime.h>
#include <cuda_bf16.h>
#include <cstdint>
#include <math.h>

#define T_STEPS 512
#define BATCH   64
#define IN_F    512
#define HID     512
#define GATES   1024
#define SCAN_CTAS 64          // 64 CTAs x 8 hidden columns: halves L2 h-broadcast

// gi tensor-core GEMM tiling (unchanged, verified R9/R10)
#define GI_KC    32
#define GSTRIDE  36
#define GI_SMEM_BYTES (4 * 128 * GSTRIDE * 4)

// scan smem layout (bytes)
#define HROW        520                          // bf16 row stride: 1040B -> conflict-free ldsm
#define PLANE_BYTES (BATCH * HROW * 2)           // 66560
#define RED_OFF     (2 * PLANE_BYTES)            // 133120
#define SCAN_SMEM_BYTES (RED_OFF + 4 * 64 * 16 * 4)  // +16KB reduction = 149504

// scratch: input gates + per-step bf16 hi/lo h planes
__device__ float g_gi[(size_t)T_STEPS * BATCH * GATES];
__device__ unsigned short g_hhi[(size_t)T_STEPS * BATCH * HID];
__device__ unsigned short g_hlo[(size_t)T_STEPS * BATCH * HID];
__device__ unsigned int g_bar;   // zero at load; self-reset by last CTA each run

__device__ __forceinline__ unsigned ld_acquire_gpu(const unsigned* p) {
    unsigned v;
    asm volatile("ld.acquire.gpu.global.u32 %0, [%1];" : "=r"(v) : "l"(p));
    return v;
}
__device__ __forceinline__ void red_release_gpu_add1(unsigned* p) {
    asm volatile("red.release.gpu.global.add.u32 [%0], 1;" :: "l"(p) : "memory");
}

// ---- tf32 helpers (gi GEMM, verified) ----
__device__ __forceinline__ unsigned f2tf32(float x) {
    unsigned r;
    asm("cvt.rna.tf32.f32 %0, %1;" : "=r"(r) : "f"(x));
    return r;
}
__device__ __forceinline__ void cvt_split(float x, unsigned& hi, unsigned& lo) {
    hi = f2tf32(x);
    lo = f2tf32(x - __uint_as_float(hi));
}
__device__ __forceinline__ uint32_t smem_u32(const void* p) {
    uint32_t a;
    asm("{.reg .u64 t; cvta.to.shared.u64 t, %1; cvt.u32.u64 %0, t;}" : "=r"(a) : "l"(p));
    return a;
}
__device__ __forceinline__ void ldsm4(unsigned* r, uint32_t addr) {
    asm volatile("ldmatrix.sync.aligned.m8n8.x4.shared.b16 {%0,%1,%2,%3}, [%4];"
                 : "=r"(r[0]), "=r"(r[1]), "=r"(r[2]), "=r"(r[3]) : "r"(addr));
}
__device__ __forceinline__ void mma_tf32(float* c, const unsigned* a, const unsigned* b) {
    asm volatile("mma.sync.aligned.m16n8k8.row.col.f32.tf32.tf32.f32 "
                 "{%0,%1,%2,%3}, {%4,%5,%6,%7}, {%8,%9}, {%0,%1,%2,%3};"
                 : "+f"(c[0]), "+f"(c[1]), "+f"(c[2]), "+f"(c[3])
                 : "r"(a[0]), "r"(a[1]), "r"(a[2]), "r"(a[3]), "r"(b[0]), "r"(b[1]));
}
__device__ __forceinline__ void mma_bf16(float* c, const unsigned* a, const unsigned* b) {
    asm volatile("mma.sync.aligned.m16n8k16.row.col.f32.bf16.bf16.f32 "
                 "{%0,%1,%2,%3}, {%4,%5,%6,%7}, {%8,%9}, {%0,%1,%2,%3};"
                 : "+f"(c[0]), "+f"(c[1]), "+f"(c[2]), "+f"(c[3])
                 : "r"(a[0]), "r"(a[1]), "r"(a[2]), "r"(a[3]), "r"(b[0]), "r"(b[1]));
}
__device__ __forceinline__ void cp_async16(uint32_t smem, const void* gptr) {
    asm volatile("cp.async.cg.shared.global [%0], [%1], 16;" :: "r"(smem), "l"(gptr) : "memory");
}
__device__ __forceinline__ void cp_commit_wait() {
    asm volatile("cp.async.commit_group;\ncp.async.wait_group 0;" ::: "memory");
}

// ===================== gi GEMM (unchanged from R9/R10) =====================
__global__ __launch_bounds__(512) void gi_gemm_mma(const float* __restrict__ X,
                                                   const float* __restrict__ W,
                                                   const float* __restrict__ bih) {
    extern __shared__ unsigned gsm[];
    unsigned* Ahi = gsm;
    unsigned* Alo = gsm + 128 * GSTRIDE;
    unsigned* Bhi = gsm + 2 * 128 * GSTRIDE;
    unsigned* Blo = gsm + 3 * 128 * GSTRIDE;

    const int tid  = threadIdx.x;
    const int lane = tid & 31;
    const int wid  = tid >> 5;
    const int warpM = (wid & 3) * 32;
    const int warpN = (wid >> 2) * 32;
    const int Mb = blockIdx.y * 128;
    const int Nb = blockIdx.x * 128;

    const int aRow = warpM + (lane & 15);
    const int aColOff = (lane >> 4) << 2;
    const int bRow = warpN + ((lane >> 4) << 3) + (lane & 7);
    const int bColOff = ((lane >> 3) & 1) << 2;

    float acc[2][4][4];
    #pragma unroll
    for (int mt = 0; mt < 2; mt++)
        #pragma unroll
        for (int nt = 0; nt < 4; nt++)
            #pragma unroll
            for (int i = 0; i < 4; i++) acc[mt][nt][i] = 0.f;

    const int srow = tid >> 3;
    const int sc4  = (tid & 7) * 4;

    for (int k0 = 0; k0 < IN_F; k0 += GI_KC) {
        __syncthreads();
        #pragma unroll
        for (int i = 0; i < 2; i++) {
            const int row = srow + 64 * i;
            const float4 a = *(const float4*)&X[(size_t)(Mb + row) * IN_F + k0 + sc4];
            const float4 b = *(const float4*)&W[(size_t)(Nb + row) * IN_F + k0 + sc4];
            uint4 ah, al, bh, bl;
            cvt_split(a.x, ah.x, al.x); cvt_split(a.y, ah.y, al.y);
            cvt_split(a.z, ah.z, al.z); cvt_split(a.w, ah.w, al.w);
            cvt_split(b.x, bh.x, bl.x); cvt_split(b.y, bh.y, bl.y);
            cvt_split(b.z, bh.z, bl.z); cvt_split(b.w, bh.w, bl.w);
            const int off = row * GSTRIDE + sc4;
            *(uint4*)&Ahi[off] = ah;
            *(uint4*)&Alo[off] = al;
            *(uint4*)&Bhi[off] = bh;
            *(uint4*)&Blo[off] = bl;
        }
        __syncthreads();

        #pragma unroll
        for (int k8 = 0; k8 < GI_KC / 8; k8++) {
            const int kb = k8 * 8;
            unsigned ah[2][4], al[2][4], bh[4][2], bl[4][2];
            #pragma unroll
            for (int mt = 0; mt < 2; mt++) {
                const int off = (aRow + mt * 16) * GSTRIDE + kb + aColOff;
                ldsm4(ah[mt], smem_u32(&Ahi[off]));
                ldsm4(al[mt], smem_u32(&Alo[off]));
            }
            #pragma unroll
            for (int np = 0; np < 2; np++) {
                const int off = (bRow + np * 16) * GSTRIDE + kb + bColOff;
                unsigned r[4];
                ldsm4(r, smem_u32(&Bhi[off]));
                bh[2 * np][0] = r[0]; bh[2 * np][1] = r[1];
                bh[2 * np + 1][0] = r[2]; bh[2 * np + 1][1] = r[3];
                ldsm4(r, smem_u32(&Blo[off]));
                bl[2 * np][0] = r[0]; bl[2 * np][1] = r[1];
                bl[2 * np + 1][0] = r[2]; bl[2 * np + 1][1] = r[3];
            }
            #pragma unroll
            for (int mt = 0; mt < 2; mt++)
                #pragma unroll
                for (int nt = 0; nt < 4; nt++) {
                    mma_tf32(acc[mt][nt], ah[mt], bh[nt]);
                    mma_tf32(acc[mt][nt], ah[mt], bl[nt]);
                    mma_tf32(acc[mt][nt], al[mt], bh[nt]);
                }
        }
    }

    #pragma unroll
    for (int mt = 0; mt < 2; mt++)
        #pragma unroll
        for (int nt = 0; nt < 4; nt++) {
            const int gr = Mb + warpM + mt * 16 + (lane >> 2);
            const int gc = Nb + warpN + nt * 8 + 2 * (lane & 3);
            const float2 bv = *(const float2*)&bih[gc];
            float2 v0, v1;
            v0.x = acc[mt][nt][0] + bv.x; v0.y = acc[mt][nt][1] + bv.y;
            v1.x = acc[mt][nt][2] + bv.x; v1.y = acc[mt][nt][3] + bv.y;
            *(float2*)&g_gi[(size_t)gr * GATES + gc] = v0;
            *(float2*)&g_gi[(size_t)(gr + 8) * GATES + gc] = v1;
        }
}

// ===================== tensor-core recurrent scan =====================
// 64 CTAs x 512 threads (16 warps = 4 M-tiles x 4 K-slices). Each CTA owns
// 8 hidden columns = 16 gate rows (8 f + 8 n). W fragments (split-bf16) are
// register-resident for all steps; h staged per step via cp.async.cg and
// consumed via ldmatrix + mma.m16n8k16 (3-pass split-bf16). All 512 threads
// compute gates (b = tid>>3, jl = tid&7).
__global__ __launch_bounds__(512) void scan_kernel(const float* __restrict__ Whh,
                                                   const float* __restrict__ bhh,
                                                   float* __restrict__ out) {
    extern __shared__ unsigned char smraw[];
    unsigned short* hhi = (unsigned short*)smraw;                 // [64][520]
    unsigned short* hlo = (unsigned short*)(smraw + PLANE_BYTES); // [64][520]
    float* red = (float*)(smraw + RED_OFF);                       // [4][64][16]

    const int tid  = threadIdx.x;
    const int lane = tid & 31;
    const int wid  = tid >> 5;
    const int mt   = wid & 3;           // M tile (16 rows of b)
    const int ksl  = wid >> 2;          // K slice (128 k)
    const int j0   = blockIdx.x * 8;

    // ---- one-time: stage 16 W rows as bf16 hi/lo, load B frags into regs ----
    unsigned short* Whi_s = hhi;                 // overlay (freed before step loop)
    unsigned short* Wlo_s = hhi + 16 * HROW;
    for (int i = tid; i < 16 * 512; i += 512) {
        const int n = i >> 9, c = i & 511;
        const int gr = (n < 8) ? (j0 + n) : (HID + j0 + (n - 8));
        const float w = Whh[(size_t)gr * HID + c];
        const __nv_bfloat16 h16 = __float2bfloat16(w);
        const __nv_bfloat16 l16 = __float2bfloat16(w - __bfloat162float(h16));
        Whi_s[n * HROW + c] = __bfloat16_as_ushort(h16);
        Wlo_s[n * HROW + c] = __bfloat16_as_ushort(l16);
    }
    __syncthreads();
    // B-frag x4: rows (lane&7)+8*(lane>>4) [n 0-7 then 8-15], col k0+8*((lane>>3)&1)
    unsigned wbh[8][4], wbl[8][4];
    {
        const int brow = (lane & 7) + ((lane >> 4) << 3);
        const int bcol = ((lane >> 3) & 1) * 8;
        #pragma unroll
        for (int s = 0; s < 8; s++) {
            const int k0 = ksl * 128 + s * 16;
            ldsm4(wbh[s], smem_u32(&Whi_s[brow * HROW + k0 + bcol]));
            ldsm4(wbl[s], smem_u32(&Wlo_s[brow * HROW + k0 + bcol]));
        }
    }
    __syncthreads();   // W smem region now reusable for h planes

    // A-frag ldmatrix row (constant): rows m0..m0+15, col groups of 8
    const int arow  = mt * 16 + (lane & 7) + 8 * ((lane >> 3) & 1);
    const int acol8 = (lane >> 4) * 8;
    const uint32_t ahi_base = smem_u32(&hhi[arow * HROW]);
    const uint32_t alo_base = smem_u32(&hlo[arow * HROW]);

    // gate-thread constants: every thread owns one (b, jl) output
    const int jl = tid & 7;
    const int b  = tid >> 3;
    const int jg = j0 + jl;
    const float bhf = bhh[jg];
    const float bhn = bhh[HID + jg];
    float gif = g_gi[((size_t)b << 10) + jg];
    float gin = g_gi[((size_t)b << 10) + HID + jg];

    for (int t = 0; t < T_STEPS; t++) {
        if (t > 0) {
            // grid barrier: 1 arriver + 1 poller per CTA (flat counter)
            __syncthreads();
            if (tid == 0) {
                red_release_gpu_add1(&g_bar);
                const unsigned target = (unsigned)SCAN_CTAS * (unsigned)t;
                while (ld_acquire_gpu(&g_bar) < target) __nanosleep(32);
            }
            __syncthreads();
        }

        // prefetch next step's gi (h-independent)
        const int tn = (t + 1 < T_STEPS) ? (t + 1) : t;
        const float gif_n = g_gi[((size_t)tn << 16) + ((size_t)b << 10) + jg];
        const float gin_n = g_gi[((size_t)tn << 16) + ((size_t)b << 10) + HID + jg];

        float accf = 0.f, accn = 0.f;
        if (t > 0) {
            // ---- stage h(t-1) bf16 planes into smem (L1-bypassing 16B copies) ----
            const unsigned short* ph = g_hhi + (size_t)(t - 1) * BATCH * HID;
            const unsigned short* pl = g_hlo + (size_t)(t - 1) * BATCH * HID;
            #pragma unroll
            for (int i = 0; i < 8; i++) {
                const int idx = tid + 512 * i;          // 16B chunk index
                const int br = idx >> 6, c = idx & 63;
                cp_async16(smem_u32(&hhi[br * HROW + c * 8]), ph + idx * 8);
                cp_async16(smem_u32(&hlo[br * HROW + c * 8]), pl + idx * 8);
            }
            cp_commit_wait();
            __syncthreads();

            // ---- split-bf16 MMA: D[64x16] partial over this warp's 128 k ----
            float c4[2][4] = {{0.f, 0.f, 0.f, 0.f}, {0.f, 0.f, 0.f, 0.f}};
            #pragma unroll
            for (int s = 0; s < 8; s++) {
                const int k0 = ksl * 128 + s * 16;
                unsigned ah[4], al[4];
                ldsm4(ah, ahi_base + (k0 + acol8) * 2);
                ldsm4(al, alo_base + (k0 + acol8) * 2);
                #pragma unroll
                for (int nt = 0; nt < 2; nt++) {
                    mma_bf16(c4[nt], ah, &wbh[s][2 * nt]);   // hi*hi
                    mma_bf16(c4[nt], ah, &wbl[s][2 * nt]);   // hi*lo
                    mma_bf16(c4[nt], al, &wbh[s][2 * nt]);   // lo*hi
                }
            }
            // partials -> red[ksl][m][n]  (n: 0-7 = f, 8-15 = n-gate)
            const int rm = mt * 16 + (lane >> 2);
            const int rn = 2 * (lane & 3);
            #pragma unroll
            for (int nt = 0; nt < 2; nt++) {
                *(float2*)&red[ksl * 1024 + rm * 16 + nt * 8 + rn] =
                    make_float2(c4[nt][0], c4[nt][1]);
                *(float2*)&red[ksl * 1024 + (rm + 8) * 16 + nt * 8 + rn] =
                    make_float2(c4[nt][2], c4[nt][3]);
            }
            __syncthreads();

            #pragma unroll
            for (int k = 0; k < 4; k++) {
                accf += red[k * 1024 + b * 16 + jl];
                accn += red[k * 1024 + b * 16 + 8 + jl];
            }
        }

        // gates + write h_t (fp32 out + bf16 hi/lo planes)
        {
            const float f  = 1.f / (1.f + expf(-(gif + accf + bhf)));
            const float hv = tanhf(gin + f * (accn + bhn));
            out[((size_t)t * BATCH + b) * HID + jg] = hv;
            const __nv_bfloat16 h16 = __float2bfloat16(hv);
            const __nv_bfloat16 l16 = __float2bfloat16(hv - __bfloat162float(h16));
            g_hhi[(size_t)t * BATCH * HID + b * HID + jg] = __bfloat16_as_ushort(h16);
            g_hlo[(size_t)t * BATCH * HID + b * HID + jg] = __bfloat16_as_ushort(l16);
        }
        gif = gif_n;
        gin = gin_n;
    }

    // self-reset barrier for next graph replay: last arriving CTA clears it.
    __syncthreads();
    if (tid == 0) {
        const unsigned r = atomicAdd(&g_bar, 1u);
        if (r == (unsigned)SCAN_CTAS * (unsigned)T_STEPS - 1u)
            *((volatile unsigned*)&g_bar) = 0u;
    }
}

extern "C" void kernel_launch(void* const* d_in, const int* in_sizes, int n_in,
                              void* d_out, int out_size) {
    const float* X   = (const float*)d_in[0];  // (512, 64, 512)
    const float* Wih = (const float*)d_in[1];  // (1024, 512)
    const float* Whh = (const float*)d_in[2];  // (1024, 512)
    const float* bih = (const float*)d_in[3];  // (1024,)
    const float* bhh = (const float*)d_in[4];  // (1024,)
    float* out = (float*)d_out;                // (512, 64, 512)

    cudaFuncSetAttribute(gi_gemm_mma,
                         cudaFuncAttributeMaxDynamicSharedMemorySize, GI_SMEM_BYTES);
    cudaFuncSetAttribute(scan_kernel,
                         cudaFuncAttributeMaxDynamicSharedMemorySize, SCAN_SMEM_BYTES);

    dim3 g1(GATES / 128, (T_STEPS * BATCH) / 128);
    gi_gemm_mma<<<g1, 512, GI_SMEM_BYTES>>>(X, Wih, bih);
    scan_kernel<<<SCAN_CTAS, 512, SCAN_SMEM_BYTES>>>(Whh, bhh, out);
}

// round 12
// speedup vs baseline: 2.5950x; 1.2584x over previous
#include <cuda_runtime.h>
#include <cuda_bf16.h>
#include <cstdint>
#include <math.h>

#define T_STEPS 512
#define BATCH   64
#define IN_F    512
#define HID     512
#define GATES   1024

// scan decomposition: 4 independent batch groups x 16 CTAs
#define N_GROUPS   4
#define GROUP_CTAS 16
#define GB         16            // batch rows per group
#define CTA_COLS   32            // hidden columns per CTA

// gi tensor-core GEMM tiling (unchanged, verified R9-R11)
#define GI_KC    32
#define GSTRIDE  36
#define GI_SMEM_BYTES (4 * 128 * GSTRIDE * 4)

// scan smem layout
#define HROW        520                          // ushort row stride -> conflict-free ldsm
#define PLANE_USH   (GB * HROW)                  // 8320 ushorts = 16640 B
#define RED_OFF_B   (2 * PLANE_USH * 2)          // 33280 B
#define RED_FLOATS  (4 * GB * 64)                // [ksl][b][64 gate rows] = 4096
#define SCAN_SMEM_BYTES (64 * HROW * 2 * 2 + 2048)   // W overlay (133120) + pad

// scratch: input gates + per-step bf16 hi/lo h planes
__device__ float g_gi[(size_t)T_STEPS * BATCH * GATES];
__device__ unsigned short g_hhi[(size_t)T_STEPS * BATCH * HID];
__device__ unsigned short g_hlo[(size_t)T_STEPS * BATCH * HID];
__device__ unsigned int g_bars[N_GROUPS * 32];   // per-group counters, 128B apart

__device__ __forceinline__ unsigned ld_acquire_gpu(const unsigned* p) {
    unsigned v;
    asm volatile("ld.acquire.gpu.global.u32 %0, [%1];" : "=r"(v) : "l"(p));
    return v;
}
__device__ __forceinline__ void red_release_gpu_add1(unsigned* p) {
    asm volatile("red.release.gpu.global.add.u32 [%0], 1;" :: "l"(p) : "memory");
}

// ---- tf32 helpers (gi GEMM, verified) ----
__device__ __forceinline__ unsigned f2tf32(float x) {
    unsigned r;
    asm("cvt.rna.tf32.f32 %0, %1;" : "=r"(r) : "f"(x));
    return r;
}
__device__ __forceinline__ void cvt_split(float x, unsigned& hi, unsigned& lo) {
    hi = f2tf32(x);
    lo = f2tf32(x - __uint_as_float(hi));
}
__device__ __forceinline__ uint32_t smem_u32(const void* p) {
    uint32_t a;
    asm("{.reg .u64 t; cvta.to.shared.u64 t, %1; cvt.u32.u64 %0, t;}" : "=r"(a) : "l"(p));
    return a;
}
__device__ __forceinline__ void ldsm4(unsigned* r, uint32_t addr) {
    asm volatile("ldmatrix.sync.aligned.m8n8.x4.shared.b16 {%0,%1,%2,%3}, [%4];"
                 : "=r"(r[0]), "=r"(r[1]), "=r"(r[2]), "=r"(r[3]) : "r"(addr));
}
__device__ __forceinline__ void mma_tf32(float* c, const unsigned* a, const unsigned* b) {
    asm volatile("mma.sync.aligned.m16n8k8.row.col.f32.tf32.tf32.f32 "
                 "{%0,%1,%2,%3}, {%4,%5,%6,%7}, {%8,%9}, {%0,%1,%2,%3};"
                 : "+f"(c[0]), "+f"(c[1]), "+f"(c[2]), "+f"(c[3])
                 : "r"(a[0]), "r"(a[1]), "r"(a[2]), "r"(a[3]), "r"(b[0]), "r"(b[1]));
}
__device__ __forceinline__ void mma_bf16(float* c, const unsigned* a, const unsigned* b) {
    asm volatile("mma.sync.aligned.m16n8k16.row.col.f32.bf16.bf16.f32 "
                 "{%0,%1,%2,%3}, {%4,%5,%6,%7}, {%8,%9}, {%0,%1,%2,%3};"
                 : "+f"(c[0]), "+f"(c[1]), "+f"(c[2]), "+f"(c[3])
                 : "r"(a[0]), "r"(a[1]), "r"(a[2]), "r"(a[3]), "r"(b[0]), "r"(b[1]));
}
__device__ __forceinline__ void cp_async16(uint32_t smem, const void* gptr) {
    asm volatile("cp.async.cg.shared.global [%0], [%1], 16;" :: "r"(smem), "l"(gptr) : "memory");
}
__device__ __forceinline__ void cp_commit_wait() {
    asm volatile("cp.async.commit_group;\ncp.async.wait_group 0;" ::: "memory");
}

// ===================== gi GEMM (unchanged from R9-R11) =====================
__global__ __launch_bounds__(512) void gi_gemm_mma(const float* __restrict__ X,
                                                   const float* __restrict__ W,
                                                   const float* __restrict__ bih) {
    extern __shared__ unsigned gsm[];
    unsigned* Ahi = gsm;
    unsigned* Alo = gsm + 128 * GSTRIDE;
    unsigned* Bhi = gsm + 2 * 128 * GSTRIDE;
    unsigned* Blo = gsm + 3 * 128 * GSTRIDE;

    const int tid  = threadIdx.x;
    const int lane = tid & 31;
    const int wid  = tid >> 5;
    const int warpM = (wid & 3) * 32;
    const int warpN = (wid >> 2) * 32;
    const int Mb = blockIdx.y * 128;
    const int Nb = blockIdx.x * 128;

    const int aRow = warpM + (lane & 15);
    const int aColOff = (lane >> 4) << 2;
    const int bRow = warpN + ((lane >> 4) << 3) + (lane & 7);
    const int bColOff = ((lane >> 3) & 1) << 2;

    float acc[2][4][4];
    #pragma unroll
    for (int mt = 0; mt < 2; mt++)
        #pragma unroll
        for (int nt = 0; nt < 4; nt++)
            #pragma unroll
            for (int i = 0; i < 4; i++) acc[mt][nt][i] = 0.f;

    const int srow = tid >> 3;
    const int sc4  = (tid & 7) * 4;

    for (int k0 = 0; k0 < IN_F; k0 += GI_KC) {
        __syncthreads();
        #pragma unroll
        for (int i = 0; i < 2; i++) {
            const int row = srow + 64 * i;
            const float4 a = *(const float4*)&X[(size_t)(Mb + row) * IN_F + k0 + sc4];
            const float4 b = *(const float4*)&W[(size_t)(Nb + row) * IN_F + k0 + sc4];
            uint4 ah, al, bh, bl;
            cvt_split(a.x, ah.x, al.x); cvt_split(a.y, ah.y, al.y);
            cvt_split(a.z, ah.z, al.z); cvt_split(a.w, ah.w, al.w);
            cvt_split(b.x, bh.x, bl.x); cvt_split(b.y, bh.y, bl.y);
            cvt_split(b.z, bh.z, bl.z); cvt_split(b.w, bh.w, bl.w);
            const int off = row * GSTRIDE + sc4;
            *(uint4*)&Ahi[off] = ah;
            *(uint4*)&Alo[off] = al;
            *(uint4*)&Bhi[off] = bh;
            *(uint4*)&Blo[off] = bl;
        }
        __syncthreads();

        #pragma unroll
        for (int k8 = 0; k8 < GI_KC / 8; k8++) {
            const int kb = k8 * 8;
            unsigned ah[2][4], al[2][4], bh[4][2], bl[4][2];
            #pragma unroll
            for (int mt = 0; mt < 2; mt++) {
                const int off = (aRow + mt * 16) * GSTRIDE + kb + aColOff;
                ldsm4(ah[mt], smem_u32(&Ahi[off]));
                ldsm4(al[mt], smem_u32(&Alo[off]));
            }
            #pragma unroll
            for (int np = 0; np < 2; np++) {
                const int off = (bRow + np * 16) * GSTRIDE + kb + bColOff;
                unsigned r[4];
                ldsm4(r, smem_u32(&Bhi[off]));
                bh[2 * np][0] = r[0]; bh[2 * np][1] = r[1];
                bh[2 * np + 1][0] = r[2]; bh[2 * np + 1][1] = r[3];
                ldsm4(r, smem_u32(&Blo[off]));
                bl[2 * np][0] = r[0]; bl[2 * np][1] = r[1];
                bl[2 * np + 1][0] = r[2]; bl[2 * np + 1][1] = r[3];
            }
            #pragma unroll
            for (int mt = 0; mt < 2; mt++)
                #pragma unroll
                for (int nt = 0; nt < 4; nt++) {
                    mma_tf32(acc[mt][nt], ah[mt], bh[nt]);
                    mma_tf32(acc[mt][nt], ah[mt], bl[nt]);
                    mma_tf32(acc[mt][nt], al[mt], bh[nt]);
                }
        }
    }

    #pragma unroll
    for (int mt = 0; mt < 2; mt++)
        #pragma unroll
        for (int nt = 0; nt < 4; nt++) {
            const int gr = Mb + warpM + mt * 16 + (lane >> 2);
            const int gc = Nb + warpN + nt * 8 + 2 * (lane & 3);
            const float2 bv = *(const float2*)&bih[gc];
            float2 v0, v1;
            v0.x = acc[mt][nt][0] + bv.x; v0.y = acc[mt][nt][1] + bv.y;
            v1.x = acc[mt][nt][2] + bv.x; v1.y = acc[mt][nt][3] + bv.y;
            *(float2*)&g_gi[(size_t)gr * GATES + gc] = v0;
            *(float2*)&g_gi[(size_t)(gr + 8) * GATES + gc] = v1;
        }
}

// ===================== tensor-core recurrent scan, batch-grouped ==========
// 64 CTAs = 4 independent groups x 16 CTAs. Group g owns batch rows
// [g*16, g*16+16); CTA cg in the group owns 32 hidden columns (64 gate rows).
// Per-group 16-arrival barrier; no cross-group coupling. W fragments
// register-resident; h exchanged as bf16 hi/lo planes via L2 (cp.async.cg).
__global__ __launch_bounds__(512) void scan_kernel(const float* __restrict__ Whh,
                                                   const float* __restrict__ bhh,
                                                   float* __restrict__ out) {
    extern __shared__ unsigned char smraw[];
    unsigned short* hhi = (unsigned short*)smraw;            // [16][520]
    unsigned short* hlo = hhi + PLANE_USH;                   // [16][520]
    float* red = (float*)(smraw + RED_OFF_B);                // [4][16][64]

    const int tid  = threadIdx.x;
    const int lane = tid & 31;
    const int wid  = tid >> 5;
    const int ksl  = wid >> 2;          // K slice (128 k)
    const int ng   = wid & 3;           // n-group: 16 gate rows (2 n-tiles)
    const int grp  = blockIdx.x >> 4;   // batch group 0..3
    const int cg   = blockIdx.x & 15;   // CTA within group
    const int bg0  = grp * GB;          // first batch row of group
    const int j0   = cg * CTA_COLS;     // first hidden column of CTA
    unsigned* bar  = &g_bars[grp * 32];

    // ---- one-time: stage 64 W rows (32 f + 32 n) as bf16 hi/lo, ldsm to regs
    unsigned short* Whi_s = hhi;                   // overlay, freed after init
    unsigned short* Wlo_s = hhi + 64 * HROW;
    for (int i = tid; i < 64 * 512; i += 512) {
        const int n = i >> 9, c = i & 511;
        const int gr = (n < CTA_COLS) ? (j0 + n) : (HID + j0 + (n - CTA_COLS));
        const float w = Whh[(size_t)gr * HID + c];
        const __nv_bfloat16 h16 = __float2bfloat16(w);
        const __nv_bfloat16 l16 = __float2bfloat16(w - __bfloat162float(h16));
        Whi_s[n * HROW + c] = __bfloat16_as_ushort(h16);
        Wlo_s[n * HROW + c] = __bfloat16_as_ushort(l16);
    }
    __syncthreads();
    // B frags: this warp covers gate rows [ng*16, ng*16+16) over its 128 k
    unsigned wbh[8][4], wbl[8][4];
    {
        const int brow = ng * 16 + (lane & 7) + ((lane >> 4) << 3);
        const int bcol = ((lane >> 3) & 1) * 8;
        #pragma unroll
        for (int s = 0; s < 8; s++) {
            const int k0 = ksl * 128 + s * 16;
            ldsm4(wbh[s], smem_u32(&Whi_s[brow * HROW + k0 + bcol]));
            ldsm4(wbl[s], smem_u32(&Wlo_s[brow * HROW + k0 + bcol]));
        }
    }
    __syncthreads();   // W overlay now reusable for h planes

    // A-frag address (M=16, single tile): rows 0..15 of the group's h slab
    const int arow  = (lane & 7) + 8 * ((lane >> 3) & 1);
    const int acol8 = (lane >> 4) * 8;
    const uint32_t ahi_base = smem_u32(&hhi[arow * HROW]);
    const uint32_t alo_base = smem_u32(&hlo[arow * HROW]);

    // gate-thread constants: thread owns (local b, jl)
    const int jl = tid & 31;            // hidden col within CTA
    const int bl = tid >> 5;            // local batch row 0..15
    const int b  = bg0 + bl;            // global batch row
    const int jg = j0 + jl;             // global hidden col
    const float bhf = bhh[jg];
    const float bhn = bhh[HID + jg];
    float gif = g_gi[((size_t)b << 10) + jg];
    float gin = g_gi[((size_t)b << 10) + HID + jg];

    for (int t = 0; t < T_STEPS; t++) {
        if (t > 0) {
            // per-group barrier: 16 arrivals, 1 poller per CTA
            __syncthreads();
            if (tid == 0) {
                red_release_gpu_add1(bar);
                const unsigned target = (unsigned)GROUP_CTAS * (unsigned)t;
                while (ld_acquire_gpu(bar) < target) __nanosleep(32);
            }
            __syncthreads();
        }

        // prefetch next step's gi (h-independent)
        const int tn = (t + 1 < T_STEPS) ? (t + 1) : t;
        const float gif_n = g_gi[((size_t)tn << 16) + ((size_t)b << 10) + jg];
        const float gin_n = g_gi[((size_t)tn << 16) + ((size_t)b << 10) + HID + jg];

        float accf = 0.f, accn = 0.f;
        if (t > 0) {
            // stage group's h(t-1) planes: 16 rows x 512 = 16KB per plane
            const unsigned short* ph = g_hhi + ((size_t)(t - 1) * BATCH + bg0) * HID;
            const unsigned short* pl = g_hlo + ((size_t)(t - 1) * BATCH + bg0) * HID;
            #pragma unroll
            for (int i = 0; i < 2; i++) {
                const int idx = tid + 512 * i;          // 16B chunk index (1024 total)
                const int br = idx >> 6, c = idx & 63;
                cp_async16(smem_u32(&hhi[br * HROW + c * 8]), ph + idx * 8);
                cp_async16(smem_u32(&hlo[br * HROW + c * 8]), pl + idx * 8);
            }
            cp_commit_wait();
            __syncthreads();

            // split-bf16 MMA: D[16 x 16 gate rows] partial over 128 k
            float c4[2][4] = {{0.f, 0.f, 0.f, 0.f}, {0.f, 0.f, 0.f, 0.f}};
            #pragma unroll
            for (int s = 0; s < 8; s++) {
                const int k0 = ksl * 128 + s * 16;
                unsigned ah[4], al[4];
                ldsm4(ah, ahi_base + (k0 + acol8) * 2);
                ldsm4(al, alo_base + (k0 + acol8) * 2);
                #pragma unroll
                for (int nt = 0; nt < 2; nt++) {
                    mma_bf16(c4[nt], ah, &wbh[s][2 * nt]);
                    mma_bf16(c4[nt], ah, &wbl[s][2 * nt]);
                    mma_bf16(c4[nt], al, &wbh[s][2 * nt]);
                }
            }
            // partials -> red[ksl][b][gate row 0..63]
            const int rm = lane >> 2;
            const int rn = ng * 16 + 2 * (lane & 3);
            #pragma unroll
            for (int nt = 0; nt < 2; nt++) {
                *(float2*)&red[ksl * (GB * 64) + rm * 64 + rn + nt * 8] =
                    make_float2(c4[nt][0], c4[nt][1]);
                *(float2*)&red[ksl * (GB * 64) + (rm + 8) * 64 + rn + nt * 8] =
                    make_float2(c4[nt][2], c4[nt][3]);
            }
            __syncthreads();

            #pragma unroll
            for (int k = 0; k < 4; k++) {
                accf += red[k * (GB * 64) + bl * 64 + jl];
                accn += red[k * (GB * 64) + bl * 64 + CTA_COLS + jl];
            }
        }

        // gates + write h_t (fp32 out + bf16 hi/lo planes)
        {
            const float f  = 1.f / (1.f + expf(-(gif + accf + bhf)));
            const float hv = tanhf(gin + f * (accn + bhn));
            out[((size_t)t * BATCH + b) * HID + jg] = hv;
            const __nv_bfloat16 h16 = __float2bfloat16(hv);
            const __nv_bfloat16 l16 = __float2bfloat16(hv - __bfloat162float(h16));
            g_hhi[(size_t)t * BATCH * HID + b * HID + jg] = __bfloat16_as_ushort(h16);
            g_hlo[(size_t)t * BATCH * HID + b * HID + jg] = __bfloat16_as_ushort(l16);
        }
        gif = gif_n;
        gin = gin_n;
    }

    // per-group self-reset: last arriving CTA of the group clears its counter.
    __syncthreads();
    if (tid == 0) {
        const unsigned r = atomicAdd(bar, 1u);
        if (r == (unsigned)GROUP_CTAS * (unsigned)T_STEPS - 1u)
            *((volatile unsigned*)bar) = 0u;
    }
}

extern "C" void kernel_launch(void* const* d_in, const int* in_sizes, int n_in,
                              void* d_out, int out_size) {
    const float* X   = (const float*)d_in[0];  // (512, 64, 512)
    const float* Wih = (const float*)d_in[1];  // (1024, 512)
    const float* Whh = (const float*)d_in[2];  // (1024, 512)
    const float* bih = (const float*)d_in[3];  // (1024,)
    const float* bhh = (const float*)d_in[4];  // (1024,)
    float* out = (float*)d_out;                // (512, 64, 512)

    cudaFuncSetAttribute(gi_gemm_mma,
                         cudaFuncAttributeMaxDynamicSharedMemorySize, GI_SMEM_BYTES);
    cudaFuncSetAttribute(scan_kernel,
                         cudaFuncAttributeMaxDynamicSharedMemorySize, SCAN_SMEM_BYTES);

    dim3 g1(GATES / 128, (T_STEPS * BATCH) / 128);
    gi_gemm_mma<<<g1, 512, GI_SMEM_BYTES>>>(X, Wih, bih);
    scan_kernel<<<N_GROUPS * GROUP_CTAS, 512, SCAN_SMEM_BYTES>>>(Whh, bhh, out);
}

// round 13
// speedup vs baseline: 3.4458x; 1.3278x over previous
#include <cuda_runtime.h>
#include <cuda_bf16.h>
#include <cstdint>
#include <math.h>

#define T_STEPS 512
#define BATCH   64
#define IN_F    512
#define HID     512
#define GATES   1024

// scan decomposition: 4 independent batch groups x 16 CTAs
#define N_GROUPS   4
#define GROUP_CTAS 16
#define GB         16
#define CTA_COLS   32
#define SCAN_BLOCKS 64

// gi tensor-core GEMM tiling (verified R9-R12)
#define GI_KC    32
#define GSTRIDE  36
#define GI_BLOCKS 2048            // 8 n-tiles x 256 m-tiles

// scan smem layout
#define HROW        520
#define PLANE_USH   (GB * HROW)
#define RED_OFF_B   (2 * PLANE_USH * 2)
#define FUSED_SMEM_BYTES (64 * HROW * 2 * 2 + 2048)   // 135168 (covers gi's 73728)

// scratch
__device__ float g_gi[(size_t)T_STEPS * BATCH * GATES];
__device__ unsigned short g_hhi[(size_t)T_STEPS * BATCH * HID];
__device__ unsigned short g_hlo[(size_t)T_STEPS * BATCH * HID];
__device__ unsigned int g_bars[N_GROUPS * 32];   // per-group scan barriers
__device__ unsigned int g_gi_cnt[256 * 8];       // per time-pair gi readiness (8 arrivals)
__device__ unsigned int g_scan_done;             // reset coordinator

__device__ __forceinline__ unsigned ld_acquire_gpu(const unsigned* p) {
    unsigned v;
    asm volatile("ld.acquire.gpu.global.u32 %0, [%1];" : "=r"(v) : "l"(p));
    return v;
}
__device__ __forceinline__ void red_release_gpu_add1(unsigned* p) {
    asm volatile("red.release.gpu.global.add.u32 [%0], 1;" :: "l"(p) : "memory");
}
__device__ __forceinline__ unsigned f2tf32(float x) {
    unsigned r;
    asm("cvt.rna.tf32.f32 %0, %1;" : "=r"(r) : "f"(x));
    return r;
}
__device__ __forceinline__ void cvt_split(float x, unsigned& hi, unsigned& lo) {
    hi = f2tf32(x);
    lo = f2tf32(x - __uint_as_float(hi));
}
__device__ __forceinline__ uint32_t smem_u32(const void* p) {
    uint32_t a;
    asm("{.reg .u64 t; cvta.to.shared.u64 t, %1; cvt.u32.u64 %0, t;}" : "=r"(a) : "l"(p));
    return a;
}
__device__ __forceinline__ void ldsm4(unsigned* r, uint32_t addr) {
    asm volatile("ldmatrix.sync.aligned.m8n8.x4.shared.b16 {%0,%1,%2,%3}, [%4];"
                 : "=r"(r[0]), "=r"(r[1]), "=r"(r[2]), "=r"(r[3]) : "r"(addr));
}
__device__ __forceinline__ void mma_tf32(float* c, const unsigned* a, const unsigned* b) {
    asm volatile("mma.sync.aligned.m16n8k8.row.col.f32.tf32.tf32.f32 "
                 "{%0,%1,%2,%3}, {%4,%5,%6,%7}, {%8,%9}, {%0,%1,%2,%3};"
                 : "+f"(c[0]), "+f"(c[1]), "+f"(c[2]), "+f"(c[3])
                 : "r"(a[0]), "r"(a[1]), "r"(a[2]), "r"(a[3]), "r"(b[0]), "r"(b[1]));
}
__device__ __forceinline__ void mma_bf16(float* c, const unsigned* a, const unsigned* b) {
    asm volatile("mma.sync.aligned.m16n8k16.row.col.f32.bf16.bf16.f32 "
                 "{%0,%1,%2,%3}, {%4,%5,%6,%7}, {%8,%9}, {%0,%1,%2,%3};"
                 : "+f"(c[0]), "+f"(c[1]), "+f"(c[2]), "+f"(c[3])
                 : "r"(a[0]), "r"(a[1]), "r"(a[2]), "r"(a[3]), "r"(b[0]), "r"(b[1]));
}
__device__ __forceinline__ void cp_async16(uint32_t smem, const void* gptr) {
    asm volatile("cp.async.cg.shared.global [%0], [%1], 16;" :: "r"(smem), "l"(gptr) : "memory");
}
__device__ __forceinline__ void cp_commit_wait() {
    asm volatile("cp.async.commit_group;\ncp.async.wait_group 0;" ::: "memory");
}

// ===================== gi GEMM role (body verified R9-R12) =====================
__device__ void gi_role(unsigned char* smraw, int g,
                        const float* __restrict__ X,
                        const float* __restrict__ W,
                        const float* __restrict__ bih) {
    unsigned* gsm = (unsigned*)smraw;
    unsigned* Ahi = gsm;
    unsigned* Alo = gsm + 128 * GSTRIDE;
    unsigned* Bhi = gsm + 2 * 128 * GSTRIDE;
    unsigned* Blo = gsm + 3 * 128 * GSTRIDE;

    const int bx = g & 7;            // n-tile
    const int by = g >> 3;           // m-tile = time pair
    const int tid  = threadIdx.x;
    const int lane = tid & 31;
    const int wid  = tid >> 5;
    const int warpM = (wid & 3) * 32;
    const int warpN = (wid >> 2) * 32;
    const int Mb = by * 128;
    const int Nb = bx * 128;

    const int aRow = warpM + (lane & 15);
    const int aColOff = (lane >> 4) << 2;
    const int bRow = warpN + ((lane >> 4) << 3) + (lane & 7);
    const int bColOff = ((lane >> 3) & 1) << 2;

    float acc[2][4][4];
    #pragma unroll
    for (int mt = 0; mt < 2; mt++)
        #pragma unroll
        for (int nt = 0; nt < 4; nt++)
            #pragma unroll
            for (int i = 0; i < 4; i++) acc[mt][nt][i] = 0.f;

    const int srow = tid >> 3;
    const int sc4  = (tid & 7) * 4;

    for (int k0 = 0; k0 < IN_F; k0 += GI_KC) {
        __syncthreads();
        #pragma unroll
        for (int i = 0; i < 2; i++) {
            const int row = srow + 64 * i;
            const float4 a = *(const float4*)&X[(size_t)(Mb + row) * IN_F + k0 + sc4];
            const float4 b = *(const float4*)&W[(size_t)(Nb + row) * IN_F + k0 + sc4];
            uint4 ah, al, bh, bl;
            cvt_split(a.x, ah.x, al.x); cvt_split(a.y, ah.y, al.y);
            cvt_split(a.z, ah.z, al.z); cvt_split(a.w, ah.w, al.w);
            cvt_split(b.x, bh.x, bl.x); cvt_split(b.y, bh.y, bl.y);
            cvt_split(b.z, bh.z, bl.z); cvt_split(b.w, bh.w, bl.w);
            const int off = row * GSTRIDE + sc4;
            *(uint4*)&Ahi[off] = ah;
            *(uint4*)&Alo[off] = al;
            *(uint4*)&Bhi[off] = bh;
            *(uint4*)&Blo[off] = bl;
        }
        __syncthreads();

        #pragma unroll
        for (int k8 = 0; k8 < GI_KC / 8; k8++) {
            const int kb = k8 * 8;
            unsigned ah[2][4], al[2][4], bh[4][2], bl[4][2];
            #pragma unroll
            for (int mt = 0; mt < 2; mt++) {
                const int off = (aRow + mt * 16) * GSTRIDE + kb + aColOff;
                ldsm4(ah[mt], smem_u32(&Ahi[off]));
                ldsm4(al[mt], smem_u32(&Alo[off]));
            }
            #pragma unroll
            for (int np = 0; np < 2; np++) {
                const int off = (bRow + np * 16) * GSTRIDE + kb + bColOff;
                unsigned r[4];
                ldsm4(r, smem_u32(&Bhi[off]));
                bh[2 * np][0] = r[0]; bh[2 * np][1] = r[1];
                bh[2 * np + 1][0] = r[2]; bh[2 * np + 1][1] = r[3];
                ldsm4(r, smem_u32(&Blo[off]));
                bl[2 * np][0] = r[0]; bl[2 * np][1] = r[1];
                bl[2 * np + 1][0] = r[2]; bl[2 * np + 1][1] = r[3];
            }
            #pragma unroll
            for (int mt = 0; mt < 2; mt++)
                #pragma unroll
                for (int nt = 0; nt < 4; nt++) {
                    mma_tf32(acc[mt][nt], ah[mt], bh[nt]);
                    mma_tf32(acc[mt][nt], ah[mt], bl[nt]);
                    mma_tf32(acc[mt][nt], al[mt], bh[nt]);
                }
        }
    }

    #pragma unroll
    for (int mt = 0; mt < 2; mt++)
        #pragma unroll
        for (int nt = 0; nt < 4; nt++) {
            const int gr = Mb + warpM + mt * 16 + (lane >> 2);
            const int gc = Nb + warpN + nt * 8 + 2 * (lane & 3);
            const float2 bv = *(const float2*)&bih[gc];
            float2 v0, v1;
            v0.x = acc[mt][nt][0] + bv.x; v0.y = acc[mt][nt][1] + bv.y;
            v1.x = acc[mt][nt][2] + bv.x; v1.y = acc[mt][nt][3] + bv.y;
            *(float2*)&g_gi[(size_t)gr * GATES + gc] = v0;
            *(float2*)&g_gi[(size_t)(gr + 8) * GATES + gc] = v1;
        }

    // publish readiness of this n-tile for time pair `by` (8 arrivals per pair)
    __threadfence();
    __syncthreads();
    if (tid == 0) red_release_gpu_add1(&g_gi_cnt[by * 8]);
}

// ===================== scan role (body verified R12) =====================
__device__ void scan_role(unsigned char* smraw,
                          const float* __restrict__ Whh,
                          const float* __restrict__ bhh,
                          float* __restrict__ out) {
    unsigned short* hhi = (unsigned short*)smraw;
    unsigned short* hlo = hhi + PLANE_USH;
    float* red = (float*)(smraw + RED_OFF_B);

    const int tid  = threadIdx.x;
    const int lane = tid & 31;
    const int wid  = tid >> 5;
    const int ksl  = wid >> 2;
    const int ng   = wid & 3;
    const int grp  = blockIdx.x >> 4;
    const int cg   = blockIdx.x & 15;
    const int bg0  = grp * GB;
    const int j0   = cg * CTA_COLS;
    unsigned* bar  = &g_bars[grp * 32];

    // one-time: stage 64 W rows as bf16 hi/lo, ldsm into registers
    unsigned short* Whi_s = hhi;
    unsigned short* Wlo_s = hhi + 64 * HROW;
    for (int i = tid; i < 64 * 512; i += 512) {
        const int n = i >> 9, c = i & 511;
        const int gr = (n < CTA_COLS) ? (j0 + n) : (HID + j0 + (n - CTA_COLS));
        const float w = Whh[(size_t)gr * HID + c];
        const __nv_bfloat16 h16 = __float2bfloat16(w);
        const __nv_bfloat16 l16 = __float2bfloat16(w - __bfloat162float(h16));
        Whi_s[n * HROW + c] = __bfloat16_as_ushort(h16);
        Wlo_s[n * HROW + c] = __bfloat16_as_ushort(l16);
    }
    __syncthreads();
    unsigned wbh[8][4], wbl[8][4];
    {
        const int brow = ng * 16 + (lane & 7) + ((lane >> 4) << 3);
        const int bcol = ((lane >> 3) & 1) * 8;
        #pragma unroll
        for (int s = 0; s < 8; s++) {
            const int k0 = ksl * 128 + s * 16;
            ldsm4(wbh[s], smem_u32(&Whi_s[brow * HROW + k0 + bcol]));
            ldsm4(wbl[s], smem_u32(&Wlo_s[brow * HROW + k0 + bcol]));
        }
    }
    __syncthreads();

    const int arow  = (lane & 7) + 8 * ((lane >> 3) & 1);
    const int acol8 = (lane >> 4) * 8;
    const uint32_t ahi_base = smem_u32(&hhi[arow * HROW]);
    const uint32_t alo_base = smem_u32(&hlo[arow * HROW]);

    const int jl = tid & 31;
    const int bl = tid >> 5;
    const int b  = bg0 + bl;
    const int jg = j0 + jl;
    const float bhf = bhh[jg];
    const float bhn = bhh[HID + jg];

    // wait for gi time-pair 0 before first loads
    if (tid == 0) {
        while (ld_acquire_gpu(&g_gi_cnt[0]) < 8) __nanosleep(64);
    }
    __syncthreads();
    int last_ready = 0;   // meaningful in tid 0 only

    float gif = g_gi[((size_t)b << 10) + jg];
    float gin = g_gi[((size_t)b << 10) + HID + jg];

    for (int t = 0; t < T_STEPS; t++) {
        if (t > 0) {
            __syncthreads();
            if (tid == 0) {
                red_release_gpu_add1(bar);
                const unsigned target = (unsigned)GROUP_CTAS * (unsigned)t;
                while (ld_acquire_gpu(bar) < target) __nanosleep(32);
                // gi readiness for the pair containing t+1 (monotonic cache)
                const int qn = ((t + 1 < T_STEPS) ? (t + 1) : t) >> 1;
                if (qn > last_ready) {
                    while (ld_acquire_gpu(&g_gi_cnt[qn * 8]) < 8) __nanosleep(32);
                    last_ready = qn;
                }
            }
            __syncthreads();
        }

        const int tn = (t + 1 < T_STEPS) ? (t + 1) : t;
        const float gif_n = g_gi[((size_t)tn << 16) + ((size_t)b << 10) + jg];
        const float gin_n = g_gi[((size_t)tn << 16) + ((size_t)b << 10) + HID + jg];

        float accf = 0.f, accn = 0.f;
        if (t > 0) {
            const unsigned short* ph = g_hhi + ((size_t)(t - 1) * BATCH + bg0) * HID;
            const unsigned short* pl = g_hlo + ((size_t)(t - 1) * BATCH + bg0) * HID;
            #pragma unroll
            for (int i = 0; i < 2; i++) {
                const int idx = tid + 512 * i;
                const int br = idx >> 6, c = idx & 63;
                cp_async16(smem_u32(&hhi[br * HROW + c * 8]), ph + idx * 8);
                cp_async16(smem_u32(&hlo[br * HROW + c * 8]), pl + idx * 8);
            }
            cp_commit_wait();
            __syncthreads();

            float c4[2][4] = {{0.f, 0.f, 0.f, 0.f}, {0.f, 0.f, 0.f, 0.f}};
            #pragma unroll
            for (int s = 0; s < 8; s++) {
                const int k0 = ksl * 128 + s * 16;
                unsigned ah[4], al[4];
                ldsm4(ah, ahi_base + (k0 + acol8) * 2);
                ldsm4(al, alo_base + (k0 + acol8) * 2);
                #pragma unroll
                for (int nt = 0; nt < 2; nt++) {
                    mma_bf16(c4[nt], ah, &wbh[s][2 * nt]);
                    mma_bf16(c4[nt], ah, &wbl[s][2 * nt]);
                    mma_bf16(c4[nt], al, &wbh[s][2 * nt]);
                }
            }
            const int rm = lane >> 2;
            const int rn = ng * 16 + 2 * (lane & 3);
            #pragma unroll
            for (int nt = 0; nt < 2; nt++) {
                *(float2*)&red[ksl * (GB * 64) + rm * 64 + rn + nt * 8] =
                    make_float2(c4[nt][0], c4[nt][1]);
                *(float2*)&red[ksl * (GB * 64) + (rm + 8) * 64 + rn + nt * 8] =
                    make_float2(c4[nt][2], c4[nt][3]);
            }
            __syncthreads();

            #pragma unroll
            for (int k = 0; k < 4; k++) {
                accf += red[k * (GB * 64) + bl * 64 + jl];
                accn += red[k * (GB * 64) + bl * 64 + CTA_COLS + jl];
            }
        }

        {
            const float f  = 1.f / (1.f + expf(-(gif + accf + bhf)));
            const float hv = tanhf(gin + f * (accn + bhn));
            out[((size_t)t * BATCH + b) * HID + jg] = hv;
            const __nv_bfloat16 h16 = __float2bfloat16(hv);
            const __nv_bfloat16 l16 = __float2bfloat16(hv - __bfloat162float(h16));
            g_hhi[(size_t)t * BATCH * HID + b * HID + jg] = __bfloat16_as_ushort(h16);
            g_hlo[(size_t)t * BATCH * HID + b * HID + jg] = __bfloat16_as_ushort(l16);
        }
        gif = gif_n;
        gin = gin_n;
    }

    // per-group barrier self-reset + global reset coordination
    __syncthreads();
    if (tid == 0) {
        const unsigned r = atomicAdd(bar, 1u);
        if (r == (unsigned)GROUP_CTAS * (unsigned)T_STEPS - 1u)
            *((volatile unsigned*)bar) = 0u;
        red_release_gpu_add1(&g_scan_done);
        if (blockIdx.x == 0) {
            while (ld_acquire_gpu(&g_scan_done) < (unsigned)SCAN_BLOCKS) __nanosleep(64);
            for (int q = 0; q < 256; q++)
                *((volatile unsigned*)&g_gi_cnt[q * 8]) = 0u;
            *((volatile unsigned*)&g_scan_done) = 0u;
        }
    }
}

// ===================== fused kernel =====================
__global__ __launch_bounds__(512) void fused_mgu(const float* __restrict__ X,
                                                 const float* __restrict__ Wih,
                                                 const float* __restrict__ bih,
                                                 const float* __restrict__ Whh,
                                                 const float* __restrict__ bhh,
                                                 float* __restrict__ out) {
    extern __shared__ unsigned char smraw[];
    if (blockIdx.x < SCAN_BLOCKS) {
        scan_role(smraw, Whh, bhh, out);
    } else {
        gi_role(smraw, (int)blockIdx.x - SCAN_BLOCKS, X, Wih, bih);
    }
}

extern "C" void kernel_launch(void* const* d_in, const int* in_sizes, int n_in,
                              void* d_out, int out_size) {
    const float* X   = (const float*)d_in[0];  // (512, 64, 512)
    const float* Wih = (const float*)d_in[1];  // (1024, 512)
    const float* Whh = (const float*)d_in[2];  // (1024, 512)
    const float* bih = (const float*)d_in[3];  // (1024,)
    const float* bhh = (const float*)d_in[4];  // (1024,)
    float* out = (float*)d_out;                // (512, 64, 512)

    cudaFuncSetAttribute(fused_mgu,
                         cudaFuncAttributeMaxDynamicSharedMemorySize, FUSED_SMEM_BYTES);

    fused_mgu<<<SCAN_BLOCKS + GI_BLOCKS, 512, FUSED_SMEM_BYTES>>>(
        X, Wih, bih, Whh, bhh, out);
}